// round 1
// baseline (speedup 1.0000x reference)
#include <cuda_runtime.h>
#include <math.h>

#define Bn 8
#define Cn 256
#define Hn 64
#define Wn 64
#define NHn 4
#define HDn 64
#define NTOK 1024
#define KFn 256

// ---------------- static scratch (no allocation allowed) ----------------
__device__ float g_xd[Bn*Cn*1024];            // [b][c][32*32]
__device__ float g_qkvT_c[Bn*NHn*192*NTOK];   // rows 0..63 qT, 64..127 kT, 128..191 vT
__device__ float g_qkvT_f[Bn*NHn*192*NTOK];
__device__ float g_S[Bn*NHn*NTOK*NTOK];       // attn logits/probs (reused coarse->fine)
__device__ float g_score[Bn*NHn*NTOK];
__device__ int   g_topk[Bn*NHn*KFn];
__device__ float g_outc[Bn*Cn*1024];          // coarse attn out, [b][c][n]
__device__ float g_col[Bn*4096*1024];         // im2col scratch (down conv, then up conv)
__device__ float g_Wp[4*Cn*1024];             // up-conv weights per output parity
__device__ float g_coarse4[Bn*4*Cn*1024];
__device__ float g_coarse[Bn*Cn*Hn*Wn];
__device__ float g_tokfT[Bn*NHn*HDn*NTOK];
__device__ float g_outfT[Bn*NHn*HDn*NTOK];
__device__ float g_y0[Bn*Cn*Hn*Wn];
__device__ float g_t1[Bn*Cn*Hn*Wn];
__device__ float g_bn1sc[Cn], g_bn1sh[Cn], g_bn2sc[Cn], g_bn2sh[Cn];

// ---------------- generic tiled fp32 GEMM ----------------
// TA=0: A is MxK (row-major, lda); TA=1: A is KxM (lda = M-stride)
// TB=0: B is KxN ; TB=1: B is NxK
// C[m][n] = clamp((sum_k a*b)*alpha*rowScale[m] + rowShift[m], lo, hi)
template<bool TA, bool TB>
__global__ __launch_bounds__(256) void gemm_kernel(
    const float* __restrict__ A, const float* __restrict__ B, float* __restrict__ C,
    int M, int N, int K, int lda, int ldb, int ldc,
    long long sA, long long sB, long long sC,
    float alpha, const float* __restrict__ rowScale, const float* __restrict__ rowShift,
    float lo, float hi)
{
    __shared__ float As[16][64];
    __shared__ float Bs[16][64];
    const int z = blockIdx.z;
    A += z * sA; B += z * sB; C += z * sC;
    const int m0 = blockIdx.y * 64, n0 = blockIdx.x * 64;
    const int tid = threadIdx.x;
    const int tx = tid & 15, ty = tid >> 4;
    float acc[4][4] = {};

    for (int k0 = 0; k0 < K; k0 += 16) {
        if (TA) {                       // A: K x M, coalesced along m
            int kk = tid >> 4;
            int mm = (tid & 15) * 4;
            float4 a = *(const float4*)&A[(size_t)(k0 + kk) * lda + m0 + mm];
            *(float4*)&As[kk][mm] = a;
        } else {                        // A: M x K, coalesced along k, transpose in smem
            int mm = tid & 63;
            int kk = (tid >> 6) * 4;
            float4 a = *(const float4*)&A[(size_t)(m0 + mm) * lda + k0 + kk];
            As[kk+0][mm] = a.x; As[kk+1][mm] = a.y; As[kk+2][mm] = a.z; As[kk+3][mm] = a.w;
        }
        if (!TB) {                      // B: K x N
            int kk = tid >> 4;
            int nn = (tid & 15) * 4;
            float4 b = *(const float4*)&B[(size_t)(k0 + kk) * ldb + n0 + nn];
            *(float4*)&Bs[kk][nn] = b;
        } else {                        // B: N x K
            int nn = tid & 63;
            int kk = (tid >> 6) * 4;
            float4 b = *(const float4*)&B[(size_t)(n0 + nn) * ldb + k0 + kk];
            Bs[kk+0][nn] = b.x; Bs[kk+1][nn] = b.y; Bs[kk+2][nn] = b.z; Bs[kk+3][nn] = b.w;
        }
        __syncthreads();
        #pragma unroll
        for (int kk = 0; kk < 16; ++kk) {
            float av[4], bv[4];
            *(float4*)av = *(const float4*)&As[kk][ty*4];
            *(float4*)bv = *(const float4*)&Bs[kk][tx*4];
            #pragma unroll
            for (int i = 0; i < 4; i++)
                #pragma unroll
                for (int j = 0; j < 4; j++)
                    acc[i][j] = fmaf(av[i], bv[j], acc[i][j]);
        }
        __syncthreads();
    }

    #pragma unroll
    for (int i = 0; i < 4; i++) {
        int m = m0 + ty*4 + i;
        float sc = rowScale ? rowScale[m] : 1.f;
        float sh = rowShift ? rowShift[m] : 0.f;
        float4 r;
        r.x = fminf(fmaxf(acc[i][0]*alpha*sc + sh, lo), hi);
        r.y = fminf(fmaxf(acc[i][1]*alpha*sc + sh, lo), hi);
        r.z = fminf(fmaxf(acc[i][2]*alpha*sc + sh, lo), hi);
        r.w = fminf(fmaxf(acc[i][3]*alpha*sc + sh, lo), hi);
        *(float4*)&C[(size_t)m*ldc + n0 + tx*4] = r;
    }
}

// ---------------- elementwise / helper kernels ----------------
__global__ void k_bnprep(const float* __restrict__ g, const float* __restrict__ b,
                         const float* __restrict__ m, const float* __restrict__ v,
                         float* __restrict__ sc, float* __restrict__ sh) {
    int i = threadIdx.x;
    if (i < Cn) {
        float inv = g[i] / sqrtf(v[i] + 1e-5f);
        sc[i] = inv;
        sh[i] = b[i] - m[i] * inv;
    }
}

__global__ void k_im2col_down(const float* __restrict__ x) {
    long long idx = (long long)blockIdx.x * 256 + threadIdx.x;   // Bn*4096*1024
    if (idx >= (long long)Bn*4096*1024) return;
    int n  = (int)(idx & 1023);
    int k  = (int)((idx >> 10) & 4095);
    int b  = (int)(idx >> 22);
    int kw = k & 3, kh = (k >> 2) & 3, ci = k >> 4;
    int ow = n & 31, oh = n >> 5;
    int ih = oh*2 - 1 + kh, iw = ow*2 - 1 + kw;
    float v = 0.f;
    if (ih >= 0 && ih < Hn && iw >= 0 && iw < Wn)
        v = x[((long long)b*Cn + ci)*(Hn*Wn) + ih*Wn + iw];
    g_col[idx] = v;
}

__global__ void k_wp(const float* __restrict__ up_w) {
    int idx = blockIdx.x * 256 + threadIdx.x;     // 4*256*1024
    if (idx >= 4*Cn*1024) return;
    int k = idx & 1023, co = (idx >> 10) & 255, p = idx >> 18;
    int tj = k & 1, ti = (k >> 1) & 1, ci = k >> 2;
    int px = p & 1, py = p >> 1;
    int kh = (py == 0) ? (ti == 0 ? 1 : 3) : (ti == 0 ? 0 : 2);
    int kw = (px == 0) ? (tj == 0 ? 1 : 3) : (tj == 0 ? 0 : 2);
    g_Wp[idx] = up_w[((ci << 8) + co) * 16 + kh*4 + kw];
}

__global__ void k_im2col_up() {
    long long idx = (long long)blockIdx.x * 256 + threadIdx.x;   // 32*1024*1024
    if (idx >= 33554432LL) return;
    int n = (int)(idx & 1023);
    int k = (int)((idx >> 10) & 1023);
    int s = (int)(idx >> 20);
    int tj = k & 1, ti = (k >> 1) & 1, ci = k >> 2;
    int px = s & 1, py = (s >> 1) & 1, b = s >> 2;
    int c = n & 31, a = n >> 5;
    int iy = (py == 0) ? (ti == 0 ? a : a - 1) : (ti == 0 ? a + 1 : a);
    int ix = (px == 0) ? (tj == 0 ? c : c - 1) : (tj == 0 ? c + 1 : c);
    float v = 0.f;
    if (iy >= 0 && iy < 32 && ix >= 0 && ix < 32)
        v = g_outc[((long long)b*Cn + ci)*1024 + iy*32 + ix];
    g_col[idx] = v;
}

__global__ void k_interleave(const float* __restrict__ unused) {
    int idx = blockIdx.x * 256 + threadIdx.x;     // 8*4*256*1024 = 2^23
    int n = idx & 1023, co = (idx >> 10) & 255, s = idx >> 18;
    int px = s & 1, py = (s >> 1) & 1, b = s >> 2;
    int c = n & 31, a = n >> 5;
    g_coarse[((long long)b*Cn + co)*4096 + (2*a + py)*64 + (2*c + px)] = g_coarse4[idx];
}

__global__ __launch_bounds__(256) void k_softmax(float* __restrict__ P) {
    __shared__ float red[8];
    long long row = blockIdx.x;
    float* p = P + row * 1024;
    int tid = threadIdx.x;
    float4 v = ((float4*)p)[tid];
    float mx = fmaxf(fmaxf(v.x, v.y), fmaxf(v.z, v.w));
    #pragma unroll
    for (int o = 16; o; o >>= 1) mx = fmaxf(mx, __shfl_xor_sync(0xffffffffu, mx, o));
    if ((tid & 31) == 0) red[tid >> 5] = mx;
    __syncthreads();
    if (tid == 0) {
        float m = red[0];
        #pragma unroll
        for (int i = 1; i < 8; i++) m = fmaxf(m, red[i]);
        red[0] = m;
    }
    __syncthreads();
    mx = red[0];
    __syncthreads();
    float e0 = __expf(v.x - mx), e1 = __expf(v.y - mx);
    float e2 = __expf(v.z - mx), e3 = __expf(v.w - mx);
    float s = (e0 + e1) + (e2 + e3);
    #pragma unroll
    for (int o = 16; o; o >>= 1) s += __shfl_xor_sync(0xffffffffu, s, o);
    if ((tid & 31) == 0) red[tid >> 5] = s;
    __syncthreads();
    if (tid == 0) {
        float t = 0.f;
        #pragma unroll
        for (int i = 0; i < 8; i++) t += red[i];
        red[0] = t;
    }
    __syncthreads();
    float inv = 1.f / red[0];
    v.x = e0 * inv; v.y = e1 * inv; v.z = e2 * inv; v.w = e3 * inv;
    ((float4*)p)[tid] = v;
}

__global__ void k_colsum(const float* __restrict__ P) {
    int z = blockIdx.x >> 2;
    int m = ((blockIdx.x & 3) << 8) + threadIdx.x;
    const float* p = P + (long long)z * 1048576 + m;
    float s = 0.f;
    #pragma unroll 8
    for (int n = 0; n < 1024; n++) s += p[(long long)n << 10];
    g_score[z * 1024 + m] = s;
}

__global__ __launch_bounds__(512) void k_topk() {
    __shared__ float v[1024];
    __shared__ int   ix[1024];
    int z = blockIdx.x, tid = threadIdx.x;
    for (int i = tid; i < 1024; i += 512) { v[i] = g_score[z*1024 + i]; ix[i] = i; }
    __syncthreads();
    for (int k = 2; k <= 1024; k <<= 1) {
        for (int j = k >> 1; j > 0; j >>= 1) {
            for (int i = tid; i < 1024; i += 512) {
                int l = i ^ j;
                if (l > i) {
                    bool up = ((i & k) == 0);   // descending overall
                    bool sw = up ? (v[i] < v[l]) : (v[i] > v[l]);
                    if (sw) {
                        float tv = v[i]; v[i] = v[l]; v[l] = tv;
                        int ti2 = ix[i]; ix[i] = ix[l]; ix[l] = ti2;
                    }
                }
            }
            __syncthreads();
        }
    }
    for (int i = tid; i < KFn; i += 512) g_topk[z*KFn + i] = ix[i];
}

__global__ void k_gather_fine() {
    int idx = blockIdx.x * 256 + threadIdx.x;    // 32*64*1024 = 2^21
    int t = idx & 1023, d = (idx >> 10) & 63, z = idx >> 16;
    int ki = t >> 2, i = (t >> 1) & 1, j = t & 1;
    int p = g_topk[(z << 8) + ki];
    int pi = p >> 5, pj = p & 31;
    int b = z >> 2, h = z & 3;
    g_tokfT[idx] = g_coarse[((long long)b*Cn + (h*HDn + d))*4096 + (2*pi + i)*64 + (2*pj + j)];
}

__global__ void k_copy() {
    int idx = blockIdx.x * 256 + threadIdx.x;    // 2^23
    g_y0[idx] = g_coarse[idx];
}

__global__ void k_scatter() {
    int idx = blockIdx.x * 256 + threadIdx.x;    // 2^21
    int t = idx & 1023, d = (idx >> 10) & 63, z = idx >> 16;
    int ki = t >> 2, i = (t >> 1) & 1, j = t & 1;
    int p = g_topk[(z << 8) + ki];
    int pi = p >> 5, pj = p & 31;
    int b = z >> 2, h = z & 3;
    g_y0[((long long)b*Cn + (h*HDn + d))*4096 + (2*pi + i)*64 + (2*pj + j)] += g_outfT[idx];
}

__global__ void k_dw(const float* __restrict__ dw_w) {
    int idx = blockIdx.x * 256 + threadIdx.x;    // 2^23
    int xw = idx & 63, y = (idx >> 6) & 63, c = (idx >> 12) & 255, b = idx >> 20;
    const float* base = g_y0 + ((long long)b*Cn + c)*4096;
    const float* wp = dw_w + c*9;
    float s = 0.f;
    #pragma unroll
    for (int ky = 0; ky < 3; ky++) {
        int yy = y + ky - 1;
        if (yy < 0 || yy >= 64) continue;
        #pragma unroll
        for (int kx = 0; kx < 3; kx++) {
            int xx = xw + kx - 1;
            if (xx < 0 || xx >= 64) continue;
            s = fmaf(base[yy*64 + xx], wp[ky*3 + kx], s);
        }
    }
    float r = s * g_bn1sc[c] + g_bn1sh[c];
    g_t1[idx] = fminf(fmaxf(r, 0.f), 6.f);
}

// ---------------- host ----------------
static void launch_gemm(bool ta, bool tb, const float* A, const float* B, float* Cc,
                        int M, int N, int K, int lda, int ldb, int ldc,
                        long long sA, long long sB, long long sC, int Z,
                        float alpha, const float* sc, const float* sh, float lo, float hi)
{
    dim3 grid(N / 64, M / 64, Z), blk(256);
    if (!ta && !tb)
        gemm_kernel<false,false><<<grid, blk>>>(A, B, Cc, M, N, K, lda, ldb, ldc, sA, sB, sC, alpha, sc, sh, lo, hi);
    else if (ta && !tb)
        gemm_kernel<true,false><<<grid, blk>>>(A, B, Cc, M, N, K, lda, ldb, ldc, sA, sB, sC, alpha, sc, sh, lo, hi);
    else
        gemm_kernel<false,true><<<grid, blk>>>(A, B, Cc, M, N, K, lda, ldb, ldc, sA, sB, sC, alpha, sc, sh, lo, hi);
}

extern "C" void kernel_launch(void* const* d_in, const int* in_sizes, int n_in,
                              void* d_out, int out_size)
{
    const float* x      = (const float*)d_in[0];
    const float* down_w = (const float*)d_in[1];
    const float* down_b = (const float*)d_in[2];
    const float* up_w   = (const float*)d_in[3];
    const float* up_b   = (const float*)d_in[4];
    const float* wqkv_c = (const float*)d_in[5];
    const float* bqkv_c = (const float*)d_in[6];
    const float* wqkv_f = (const float*)d_in[7];
    const float* bqkv_f = (const float*)d_in[8];
    const float* dw_w   = (const float*)d_in[9];
    const float* bn1_g  = (const float*)d_in[10];
    const float* bn1_b  = (const float*)d_in[11];
    const float* bn1_m  = (const float*)d_in[12];
    const float* bn1_v  = (const float*)d_in[13];
    const float* pw_w   = (const float*)d_in[14];
    const float* bn2_g  = (const float*)d_in[15];
    const float* bn2_b  = (const float*)d_in[16];
    const float* bn2_m  = (const float*)d_in[17];
    const float* bn2_v  = (const float*)d_in[18];
    float* out = (float*)d_out;

    float *p_xd, *p_qc, *p_qf, *p_S, *p_outc, *p_col, *p_Wp, *p_c4, *p_tokf, *p_outf, *p_t1;
    float *p_b1s, *p_b1h, *p_b2s, *p_b2h;
    cudaGetSymbolAddress((void**)&p_xd,   g_xd);
    cudaGetSymbolAddress((void**)&p_qc,   g_qkvT_c);
    cudaGetSymbolAddress((void**)&p_qf,   g_qkvT_f);
    cudaGetSymbolAddress((void**)&p_S,    g_S);
    cudaGetSymbolAddress((void**)&p_outc, g_outc);
    cudaGetSymbolAddress((void**)&p_col,  g_col);
    cudaGetSymbolAddress((void**)&p_Wp,   g_Wp);
    cudaGetSymbolAddress((void**)&p_c4,   g_coarse4);
    cudaGetSymbolAddress((void**)&p_tokf, g_tokfT);
    cudaGetSymbolAddress((void**)&p_outf, g_outfT);
    cudaGetSymbolAddress((void**)&p_t1,   g_t1);
    cudaGetSymbolAddress((void**)&p_b1s,  g_bn1sc);
    cudaGetSymbolAddress((void**)&p_b1h,  g_bn1sh);
    cudaGetSymbolAddress((void**)&p_b2s,  g_bn2sc);
    cudaGetSymbolAddress((void**)&p_b2h,  g_bn2sh);

    const float NEG = -3.0e38f, POS = 3.0e38f;

    // constants / weight prep
    k_bnprep<<<1, 256>>>(bn1_g, bn1_b, bn1_m, bn1_v, p_b1s, p_b1h);
    k_bnprep<<<1, 256>>>(bn2_g, bn2_b, bn2_m, bn2_v, p_b2s, p_b2h);
    k_wp<<<4096, 256>>>(up_w);

    // ---- down conv: im2col + GEMM -> xd [b][c][1024]
    k_im2col_down<<<131072, 256>>>(x);
    launch_gemm(false, false, down_w, p_col, p_xd, 256, 1024, 4096, 4096, 1024, 1024,
                0, 4096LL*1024, 256LL*1024, Bn, 1.f, nullptr, down_b, NEG, POS);

    // ---- coarse QKV: qkvT[z][192][1024] = wqkv_c^T @ xd_slice + bias
    launch_gemm(true, false, wqkv_c, p_xd, p_qc, 192, 1024, 64, 192, 1024, 1024,
                0, 65536, 192LL*1024, 32, 1.f, nullptr, bqkv_c, NEG, POS);

    // ---- coarse S = (qT)^T kT * scale
    launch_gemm(true, false, p_qc, p_qc + 65536, p_S, 1024, 1024, 64, 1024, 1024, 1024,
                196608, 196608, 1048576, 32, 0.125f, nullptr, nullptr, NEG, POS);
    k_softmax<<<32768, 256>>>(p_S);
    k_colsum<<<128, 256>>>(p_S);
    k_topk<<<32, 512>>>();

    // ---- coarse out: outc[d][n] = vT @ P^T
    launch_gemm(false, true, p_qc + 131072, p_S, p_outc, 64, 1024, 1024, 1024, 1024, 1024,
                196608, 1048576, 65536, 32, 1.f, nullptr, nullptr, NEG, POS);

    // ---- up conv transpose: 4 parity GEMMs then interleave
    k_im2col_up<<<131072, 256>>>();
    for (int par = 0; par < 4; par++) {
        launch_gemm(false, false, p_Wp + (long long)par*262144, p_col + (long long)par*1048576,
                    p_c4 + (long long)par*262144, 256, 1024, 1024, 1024, 1024, 1024,
                    0, 4194304, 1048576, Bn, 1.f, nullptr, up_b, NEG, POS);
    }
    k_interleave<<<32768, 256>>>(nullptr);

    // ---- fine attention
    k_gather_fine<<<8192, 256>>>();
    launch_gemm(true, false, wqkv_f, p_tokf, p_qf, 192, 1024, 64, 192, 1024, 1024,
                0, 65536, 192LL*1024, 32, 1.f, nullptr, bqkv_f, NEG, POS);
    launch_gemm(true, false, p_qf, p_qf + 65536, p_S, 1024, 1024, 64, 1024, 1024, 1024,
                196608, 196608, 1048576, 32, 0.125f, nullptr, nullptr, NEG, POS);
    k_softmax<<<32768, 256>>>(p_S);
    launch_gemm(false, true, p_qf + 131072, p_S, p_outf, 64, 1024, 1024, 1024, 1024, 1024,
                196608, 1048576, 65536, 32, 1.f, nullptr, nullptr, NEG, POS);

    // ---- residual combine: y0 = coarse + scattered fine output
    k_copy<<<32768, 256>>>();
    k_scatter<<<8192, 256>>>();

    // ---- depthwise 3x3 + BN1 + relu6
    k_dw<<<32768, 256>>>(dw_w);

    // ---- pointwise 1x1 + BN2 + relu6 -> out
    launch_gemm(false, false, pw_w, p_t1, out, 256, 4096, 256, 256, 4096, 4096,
                0, 1048576, 1048576, Bn, 1.f, p_b2s, p_b2h, 0.f, 6.f);
}

// round 3
// speedup vs baseline: 1.8928x; 1.8928x over previous
#include <cuda_runtime.h>
#include <cuda_bf16.h>
#include <math.h>
#include <stdint.h>

#define Bn 8
#define Cn 256
#define Hn 64
#define Wn 64
#define NHn 4
#define HDn 64
#define NTOK 1024
#define KFn 256

// ---------------- static scratch ----------------
__device__ float g_xd[Bn*Cn*1024];
__device__ float g_qkvT_c[Bn*NHn*192*NTOK];
__device__ float g_qkvT_f[Bn*NHn*192*NTOK];
__device__ float g_S[Bn*NHn*NTOK*NTOK];
__device__ float g_score[Bn*NHn*NTOK];
__device__ int   g_topk[Bn*NHn*KFn];
__device__ float g_outc[Bn*Cn*1024];
__device__ float g_col[Bn*4096*1024];
__device__ float g_Wp[4*Cn*1024];
__device__ float g_coarse4[Bn*4*Cn*1024];
__device__ float g_coarse[Bn*Cn*Hn*Wn];
__device__ float g_tokfT[Bn*NHn*HDn*NTOK];
__device__ float g_outfT[Bn*NHn*HDn*NTOK];
__device__ float g_y0[Bn*Cn*Hn*Wn];
__device__ float g_t1[Bn*Cn*Hn*Wn];
__device__ float g_bn1sc[Cn], g_bn1sh[Cn], g_bn2sc[Cn], g_bn2sh[Cn];

// ================= HMMA helpers =================
__device__ __forceinline__ void ldsm4(uint32_t* r, uint32_t addr) {
    asm volatile("ldmatrix.sync.aligned.m8n8.x4.shared.b16 {%0,%1,%2,%3}, [%4];"
                 : "=r"(r[0]), "=r"(r[1]), "=r"(r[2]), "=r"(r[3]) : "r"(addr));
}
__device__ __forceinline__ void ldsm4t(uint32_t* r, uint32_t addr) {
    asm volatile("ldmatrix.sync.aligned.m8n8.x4.trans.shared.b16 {%0,%1,%2,%3}, [%4];"
                 : "=r"(r[0]), "=r"(r[1]), "=r"(r[2]), "=r"(r[3]) : "r"(addr));
}
__device__ __forceinline__ void mma16816(float* d, const uint32_t* a, const uint32_t* b) {
    asm volatile("mma.sync.aligned.m16n8k16.row.col.f32.bf16.bf16.f32 "
                 "{%0,%1,%2,%3},{%4,%5,%6,%7},{%8,%9},{%0,%1,%2,%3};"
                 : "+f"(d[0]), "+f"(d[1]), "+f"(d[2]), "+f"(d[3])
                 : "r"(a[0]), "r"(a[1]), "r"(a[2]), "r"(a[3]), "r"(b[0]), "r"(b[1]));
}

__device__ __forceinline__ void cvt4(char* base, uint32_t off, float4 f) {
    // writes hi pair at base+off, lo pair at base+off+10240
    __nv_bfloat162 h0, h1, l0, l1;
    h0.x = __float2bfloat16_rn(f.x); h0.y = __float2bfloat16_rn(f.y);
    h1.x = __float2bfloat16_rn(f.z); h1.y = __float2bfloat16_rn(f.w);
    l0.x = __float2bfloat16_rn(f.x - __bfloat162float(h0.x));
    l0.y = __float2bfloat16_rn(f.y - __bfloat162float(h0.y));
    l1.x = __float2bfloat16_rn(f.z - __bfloat162float(h1.x));
    l1.y = __float2bfloat16_rn(f.w - __bfloat162float(h1.y));
    *(__nv_bfloat162*)(base + off)         = h0;
    *(__nv_bfloat162*)(base + off + 4)     = h1;
    *(__nv_bfloat162*)(base + off + 10240) = l0;
    *(__nv_bfloat162*)(base + off + 10244) = l1;
}
__device__ __forceinline__ void cvt1(char* base, uint32_t off, float a) {
    __nv_bfloat16 h = __float2bfloat16_rn(a);
    __nv_bfloat16 l = __float2bfloat16_rn(a - __bfloat162float(h));
    *(__nv_bfloat16*)(base + off)         = h;
    *(__nv_bfloat16*)(base + off + 10240) = l;
}

// ================= tensor-core (HMMA) GEMM =================
// C[m][n] = clamp(alpha*rowScale[m]*sum_k A[m,k]*B[n,k] + rowShift[m], lo, hi)
// ATR: A stored K x M (lda = M-stride). BKN: B stored K x N (ldb = N-stride), else N x K.
// smem: 2 stages x 4 slots (Ah, Al, Bh, Bl) x 10240B = 81920B. Epilogue reuses as fp32 stage.
#define SLOT 10240
#define STAGE (4*SLOT)
#define SMEM_HG (2*STAGE)

template<bool ATR, bool BKN>
__global__ __launch_bounds__(256) void hgemm(
    const float* __restrict__ A, const float* __restrict__ B, float* __restrict__ C,
    int M, int N, int K, int lda, int ldb, int ldc,
    long long sA, long long sB, long long sC,
    float alpha, const float* __restrict__ rowScale, const float* __restrict__ rowShift,
    float lo, float hi)
{
    extern __shared__ char sm[];
    const uint32_t smb = (uint32_t)__cvta_generic_to_shared(sm);
    const int tid = threadIdx.x;
    const int wid = tid >> 5, lane = tid & 31;
    const int grp = lane >> 2, tig = lane & 3;
    const int z = blockIdx.z;
    A += z * sA; B += z * sB; C += z * sC;
    const int m0 = blockIdx.y * 128, n0 = blockIdx.x * 128;
    const int mw = wid >> 1, nw = wid & 1;   // warp tile: 32m x 64n

    float acc[2][8][4];
    #pragma unroll
    for (int i = 0; i < 2; i++)
        #pragma unroll
        for (int j = 0; j < 8; j++)
            #pragma unroll
            for (int q = 0; q < 4; q++) acc[i][j][q] = 0.f;

    const int nch = K >> 5;          // 32 fp32 k per chunk
    float preA[16];
    float4 preB[4];

    // ---- loaders ----
    auto load_regs = [&](int c) {
        const int k0c = c << 5;
        if (!ATR) {
            #pragma unroll
            for (int p = 0; p < 4; p++) {
                int m = (tid >> 3) + (p << 5);
                int mg = min(m0 + m, M - 1);
                *(float4*)(preA + p * 4) = *(const float4*)(A + (size_t)mg * lda + k0c + ((tid & 7) << 2));
            }
        } else {
            #pragma unroll
            for (int p = 0; p < 4; p++) {
                int k = (tid >> 5) + (p << 3);
                #pragma unroll
                for (int j = 0; j < 4; j++) {
                    int mg = min(m0 + ((tid & 31) << 2) + j, M - 1);
                    preA[p * 4 + j] = A[(size_t)(k0c + k) * lda + mg];
                }
            }
        }
        if (BKN) {
            #pragma unroll
            for (int p = 0; p < 4; p++) {
                int k = (tid >> 5) + (p << 3);
                preB[p] = *(const float4*)(B + (size_t)(k0c + k) * ldb + n0 + ((tid & 31) << 2));
            }
        } else {
            #pragma unroll
            for (int p = 0; p < 4; p++) {
                int n = (tid >> 3) + (p << 5);
                preB[p] = *(const float4*)(B + (size_t)(n0 + n) * ldb + k0c + ((tid & 7) << 2));
            }
        }
    };
    auto store_regs = [&](int s) {
        char* Abase = sm + s * STAGE;
        char* Bbase = Abase + 2 * SLOT;
        if (!ATR) {
            #pragma unroll
            for (int p = 0; p < 4; p++) {
                int m = (tid >> 3) + (p << 5);
                cvt4(Abase, (uint32_t)(m * 80 + ((tid & 7) << 3)), *(float4*)(preA + p * 4));
            }
        } else {
            #pragma unroll
            for (int p = 0; p < 4; p++) {
                int k = (tid >> 5) + (p << 3);
                #pragma unroll
                for (int j = 0; j < 4; j++)
                    cvt1(Abase, (uint32_t)(k * 272 + ((((tid & 31) << 2) + j) << 1)), preA[p * 4 + j]);
            }
        }
        if (BKN) {
            #pragma unroll
            for (int p = 0; p < 4; p++) {
                int k = (tid >> 5) + (p << 3);
                cvt4(Bbase, (uint32_t)(k * 272 + ((tid & 31) << 3)), preB[p]);
            }
        } else {
            #pragma unroll
            for (int p = 0; p < 4; p++) {
                int n = (tid >> 3) + (p << 5);
                cvt4(Bbase, (uint32_t)(n * 80 + ((tid & 7) << 3)), preB[p]);
            }
        }
    };
    auto compute = [&](int s) {
        const uint32_t Ab = smb + s * STAGE;
        const uint32_t Bb = Ab + 2 * SLOT;
        const int i = lane >> 3;
        #pragma unroll
        for (int kk = 0; kk < 32; kk += 16) {
            uint32_t ah[2][4], al[2][4];
            #pragma unroll
            for (int mf = 0; mf < 2; mf++) {
                uint32_t addr;
                if (!ATR) {
                    addr = Ab + (uint32_t)((mw * 32 + mf * 16 + (lane & 15)) * 80 + (kk + (lane >> 4) * 8) * 2);
                    ldsm4(ah[mf], addr); ldsm4(al[mf], addr + SLOT);
                } else {
                    addr = Ab + (uint32_t)((kk + (i >> 1) * 8 + (lane & 7)) * 272 + (mw * 32 + mf * 16 + (i & 1) * 8) * 2);
                    ldsm4t(ah[mf], addr); ldsm4t(al[mf], addr + SLOT);
                }
            }
            #pragma unroll
            for (int nfp = 0; nfp < 4; nfp++) {
                uint32_t bh[4], bl[4], addr;
                if (BKN) {
                    addr = Bb + (uint32_t)((kk + (i & 1) * 8 + (lane & 7)) * 272 + (nw * 64 + nfp * 16 + (i >> 1) * 8) * 2);
                    ldsm4t(bh, addr); ldsm4t(bl, addr + SLOT);
                } else {
                    addr = Bb + (uint32_t)((nw * 64 + nfp * 16 + (i >> 1) * 8 + (lane & 7)) * 80 + (kk + (i & 1) * 8) * 2);
                    ldsm4(bh, addr); ldsm4(bl, addr + SLOT);
                }
                #pragma unroll
                for (int mf = 0; mf < 2; mf++) {
                    #pragma unroll
                    for (int h = 0; h < 2; h++) {
                        float* d = acc[mf][nfp * 2 + h];
                        mma16816(d, ah[mf], bh + h * 2);
                        mma16816(d, ah[mf], bl + h * 2);
                        mma16816(d, al[mf], bh + h * 2);
                    }
                }
            }
        }
    };

    // ---- pipelined mainloop ----
    load_regs(0);
    store_regs(0);
    __syncthreads();
    for (int c = 0; c < nch; c++) {
        const bool hasNext = (c + 1) < nch;
        if (hasNext) load_regs(c + 1);
        compute(c & 1);
        if (hasNext) store_regs((c + 1) & 1);
        __syncthreads();
    }

    // ---- epilogue: regs -> smem stage -> coalesced gmem ----
    float* stg = (float*)sm;   // [128][132]
    #pragma unroll
    for (int mf = 0; mf < 2; mf++) {
        int r0 = mw * 32 + mf * 16 + grp;
        int mg0 = min(m0 + r0, M - 1), mg1 = min(m0 + r0 + 8, M - 1);
        float av0 = alpha, av1 = alpha, sh0 = 0.f, sh1 = 0.f;
        if (rowScale) { av0 *= rowScale[mg0]; av1 *= rowScale[mg1]; }
        if (rowShift) { sh0 = rowShift[mg0]; sh1 = rowShift[mg1]; }
        #pragma unroll
        for (int nf = 0; nf < 8; nf++) {
            int cb = nw * 64 + nf * 8 + tig * 2;
            float* d = acc[mf][nf];
            stg[r0 * 132 + cb]           = fminf(fmaxf(d[0] * av0 + sh0, lo), hi);
            stg[r0 * 132 + cb + 1]       = fminf(fmaxf(d[1] * av0 + sh0, lo), hi);
            stg[(r0 + 8) * 132 + cb]     = fminf(fmaxf(d[2] * av1 + sh1, lo), hi);
            stg[(r0 + 8) * 132 + cb + 1] = fminf(fmaxf(d[3] * av1 + sh1, lo), hi);
        }
    }
    __syncthreads();
    #pragma unroll
    for (int it = 0; it < 16; it++) {
        int lin = tid + (it << 8);
        int rr = lin >> 5, c4 = (lin & 31) << 2;
        if (m0 + rr < M)
            *(float4*)(C + (size_t)(m0 + rr) * ldc + n0 + c4) = *(float4*)&stg[rr * 132 + c4];
    }
}

// ---------------- elementwise / helper kernels ----------------
__global__ void k_bnprep(const float* __restrict__ g, const float* __restrict__ b,
                         const float* __restrict__ m, const float* __restrict__ v,
                         float* __restrict__ sc, float* __restrict__ sh) {
    int i = threadIdx.x;
    if (i < Cn) {
        float inv = g[i] / sqrtf(v[i] + 1e-5f);
        sc[i] = inv;
        sh[i] = b[i] - m[i] * inv;
    }
}

__global__ void k_im2col_down(const float* __restrict__ x) {
    long long idx = (long long)blockIdx.x * 256 + threadIdx.x;
    if (idx >= (long long)Bn*4096*1024) return;
    int n  = (int)(idx & 1023);
    int k  = (int)((idx >> 10) & 4095);
    int b  = (int)(idx >> 22);
    int kw = k & 3, kh = (k >> 2) & 3, ci = k >> 4;
    int ow = n & 31, oh = n >> 5;
    int ih = oh*2 - 1 + kh, iw = ow*2 - 1 + kw;
    float v = 0.f;
    if (ih >= 0 && ih < Hn && iw >= 0 && iw < Wn)
        v = x[((long long)b*Cn + ci)*(Hn*Wn) + ih*Wn + iw];
    g_col[idx] = v;
}

__global__ void k_wp(const float* __restrict__ up_w) {
    int idx = blockIdx.x * 256 + threadIdx.x;
    if (idx >= 4*Cn*1024) return;
    int k = idx & 1023, co = (idx >> 10) & 255, p = idx >> 18;
    int tj = k & 1, ti = (k >> 1) & 1, ci = k >> 2;
    int px = p & 1, py = p >> 1;
    int kh = (py == 0) ? (ti == 0 ? 1 : 3) : (ti == 0 ? 0 : 2);
    int kw = (px == 0) ? (tj == 0 ? 1 : 3) : (tj == 0 ? 0 : 2);
    g_Wp[idx] = up_w[((ci << 8) + co) * 16 + kh*4 + kw];
}

__global__ void k_im2col_up() {
    long long idx = (long long)blockIdx.x * 256 + threadIdx.x;
    if (idx >= 33554432LL) return;
    int n = (int)(idx & 1023);
    int k = (int)((idx >> 10) & 1023);
    int s = (int)(idx >> 20);
    int tj = k & 1, ti = (k >> 1) & 1, ci = k >> 2;
    int px = s & 1, py = (s >> 1) & 1, b = s >> 2;
    int c = n & 31, a = n >> 5;
    int iy = (py == 0) ? (ti == 0 ? a : a - 1) : (ti == 0 ? a + 1 : a);
    int ix = (px == 0) ? (tj == 0 ? c : c - 1) : (tj == 0 ? c + 1 : c);
    float v = 0.f;
    if (iy >= 0 && iy < 32 && ix >= 0 && ix < 32)
        v = g_outc[((long long)b*Cn + ci)*1024 + iy*32 + ix];
    g_col[idx] = v;
}

__global__ void k_interleave() {
    int idx = blockIdx.x * 256 + threadIdx.x;
    int n = idx & 1023, co = (idx >> 10) & 255, s = idx >> 18;
    int px = s & 1, py = (s >> 1) & 1, b = s >> 2;
    int c = n & 31, a = n >> 5;
    g_coarse[((long long)b*Cn + co)*4096 + (2*a + py)*64 + (2*c + px)] = g_coarse4[idx];
}

__global__ __launch_bounds__(256) void k_softmax(float* __restrict__ P) {
    __shared__ float red[8];
    long long row = blockIdx.x;
    float* p = P + row * 1024;
    int tid = threadIdx.x;
    float4 v = ((float4*)p)[tid];
    float mx = fmaxf(fmaxf(v.x, v.y), fmaxf(v.z, v.w));
    #pragma unroll
    for (int o = 16; o; o >>= 1) mx = fmaxf(mx, __shfl_xor_sync(0xffffffffu, mx, o));
    if ((tid & 31) == 0) red[tid >> 5] = mx;
    __syncthreads();
    if (tid == 0) {
        float m = red[0];
        #pragma unroll
        for (int i = 1; i < 8; i++) m = fmaxf(m, red[i]);
        red[0] = m;
    }
    __syncthreads();
    mx = red[0];
    __syncthreads();
    float e0 = __expf(v.x - mx), e1 = __expf(v.y - mx);
    float e2 = __expf(v.z - mx), e3 = __expf(v.w - mx);
    float s = (e0 + e1) + (e2 + e3);
    #pragma unroll
    for (int o = 16; o; o >>= 1) s += __shfl_xor_sync(0xffffffffu, s, o);
    if ((tid & 31) == 0) red[tid >> 5] = s;
    __syncthreads();
    if (tid == 0) {
        float t = 0.f;
        #pragma unroll
        for (int i = 0; i < 8; i++) t += red[i];
        red[0] = t;
    }
    __syncthreads();
    float inv = 1.f / red[0];
    v.x = e0 * inv; v.y = e1 * inv; v.z = e2 * inv; v.w = e3 * inv;
    ((float4*)p)[tid] = v;
}

__global__ void k_colsum(const float* __restrict__ P) {
    int z = blockIdx.x >> 2;
    int m = ((blockIdx.x & 3) << 8) + threadIdx.x;
    const float* p = P + (long long)z * 1048576 + m;
    float s = 0.f;
    #pragma unroll 8
    for (int n = 0; n < 1024; n++) s += p[(long long)n << 10];
    g_score[z * 1024 + m] = s;
}

__global__ __launch_bounds__(512) void k_topk() {
    __shared__ float v[1024];
    __shared__ int   ix[1024];
    int z = blockIdx.x, tid = threadIdx.x;
    for (int i = tid; i < 1024; i += 512) { v[i] = g_score[z*1024 + i]; ix[i] = i; }
    __syncthreads();
    for (int k = 2; k <= 1024; k <<= 1) {
        for (int j = k >> 1; j > 0; j >>= 1) {
            for (int i = tid; i < 1024; i += 512) {
                int l = i ^ j;
                if (l > i) {
                    bool up = ((i & k) == 0);
                    bool sw = up ? (v[i] < v[l]) : (v[i] > v[l]);
                    if (sw) {
                        float tv = v[i]; v[i] = v[l]; v[l] = tv;
                        int ti2 = ix[i]; ix[i] = ix[l]; ix[l] = ti2;
                    }
                }
            }
            __syncthreads();
        }
    }
    for (int i = tid; i < KFn; i += 512) g_topk[z*KFn + i] = ix[i];
}

__global__ void k_gather_fine() {
    int idx = blockIdx.x * 256 + threadIdx.x;
    int t = idx & 1023, d = (idx >> 10) & 63, z = idx >> 16;
    int ki = t >> 2, i = (t >> 1) & 1, j = t & 1;
    int p = g_topk[(z << 8) + ki];
    int pi = p >> 5, pj = p & 31;
    int b = z >> 2, h = z & 3;
    g_tokfT[idx] = g_coarse[((long long)b*Cn + (h*HDn + d))*4096 + (2*pi + i)*64 + (2*pj + j)];
}

__global__ void k_copy() {
    int idx = blockIdx.x * 256 + threadIdx.x;
    g_y0[idx] = g_coarse[idx];
}

__global__ void k_scatter() {
    int idx = blockIdx.x * 256 + threadIdx.x;
    int t = idx & 1023, d = (idx >> 10) & 63, z = idx >> 16;
    int ki = t >> 2, i = (t >> 1) & 1, j = t & 1;
    int p = g_topk[(z << 8) + ki];
    int pi = p >> 5, pj = p & 31;
    int b = z >> 2, h = z & 3;
    g_y0[((long long)b*Cn + (h*HDn + d))*4096 + (2*pi + i)*64 + (2*pj + j)] += g_outfT[idx];
}

__global__ void k_dw(const float* __restrict__ dw_w) {
    int idx = blockIdx.x * 256 + threadIdx.x;
    int xw = idx & 63, y = (idx >> 6) & 63, c = (idx >> 12) & 255, b = idx >> 20;
    const float* base = g_y0 + ((long long)b*Cn + c)*4096;
    const float* wp = dw_w + c*9;
    float s = 0.f;
    #pragma unroll
    for (int ky = 0; ky < 3; ky++) {
        int yy = y + ky - 1;
        if (yy < 0 || yy >= 64) continue;
        #pragma unroll
        for (int kx = 0; kx < 3; kx++) {
            int xx = xw + kx - 1;
            if (xx < 0 || xx >= 64) continue;
            s = fmaf(base[yy*64 + xx], wp[ky*3 + kx], s);
        }
    }
    float r = s * g_bn1sc[c] + g_bn1sh[c];
    g_t1[idx] = fminf(fmaxf(r, 0.f), 6.f);
}

// ---------------- host ----------------
// mode 0: A=MxK, B=KxN ; mode 1: A=KxM, B=KxN ; mode 2: A=MxK, B=NxK
static void tg(int mode, const float* A, const float* B, float* Cc,
               int M, int N, int K, int lda, int ldb, int ldc,
               long long sA, long long sB, long long sC, int Z,
               float alpha, const float* sc, const float* sh, float lo, float hi)
{
    dim3 grid(N / 128, (M + 127) / 128, Z), blk(256);
    size_t shm = SMEM_HG;
    if (mode == 0) {
        cudaFuncSetAttribute(hgemm<false,true>, cudaFuncAttributeMaxDynamicSharedMemorySize, (int)shm);
        hgemm<false,true><<<grid, blk, shm>>>(A, B, Cc, M, N, K, lda, ldb, ldc, sA, sB, sC, alpha, sc, sh, lo, hi);
    } else if (mode == 1) {
        cudaFuncSetAttribute(hgemm<true,true>, cudaFuncAttributeMaxDynamicSharedMemorySize, (int)shm);
        hgemm<true,true><<<grid, blk, shm>>>(A, B, Cc, M, N, K, lda, ldb, ldc, sA, sB, sC, alpha, sc, sh, lo, hi);
    } else {
        cudaFuncSetAttribute(hgemm<false,false>, cudaFuncAttributeMaxDynamicSharedMemorySize, (int)shm);
        hgemm<false,false><<<grid, blk, shm>>>(A, B, Cc, M, N, K, lda, ldb, ldc, sA, sB, sC, alpha, sc, sh, lo, hi);
    }
}

extern "C" void kernel_launch(void* const* d_in, const int* in_sizes, int n_in,
                              void* d_out, int out_size)
{
    const float* x      = (const float*)d_in[0];
    const float* down_w = (const float*)d_in[1];
    const float* down_b = (const float*)d_in[2];
    const float* up_w   = (const float*)d_in[3];
    const float* up_b   = (const float*)d_in[4];
    const float* wqkv_c = (const float*)d_in[5];
    const float* bqkv_c = (const float*)d_in[6];
    const float* wqkv_f = (const float*)d_in[7];
    const float* bqkv_f = (const float*)d_in[8];
    const float* dw_w   = (const float*)d_in[9];
    const float* bn1_g  = (const float*)d_in[10];
    const float* bn1_b  = (const float*)d_in[11];
    const float* bn1_m  = (const float*)d_in[12];
    const float* bn1_v  = (const float*)d_in[13];
    const float* pw_w   = (const float*)d_in[14];
    const float* bn2_g  = (const float*)d_in[15];
    const float* bn2_b  = (const float*)d_in[16];
    const float* bn2_m  = (const float*)d_in[17];
    const float* bn2_v  = (const float*)d_in[18];
    float* out = (float*)d_out;

    float *p_xd, *p_qc, *p_qf, *p_S, *p_outc, *p_col, *p_Wp, *p_c4, *p_tokf, *p_outf, *p_t1;
    float *p_b1s, *p_b1h, *p_b2s, *p_b2h;
    cudaGetSymbolAddress((void**)&p_xd,   g_xd);
    cudaGetSymbolAddress((void**)&p_qc,   g_qkvT_c);
    cudaGetSymbolAddress((void**)&p_qf,   g_qkvT_f);
    cudaGetSymbolAddress((void**)&p_S,    g_S);
    cudaGetSymbolAddress((void**)&p_outc, g_outc);
    cudaGetSymbolAddress((void**)&p_col,  g_col);
    cudaGetSymbolAddress((void**)&p_Wp,   g_Wp);
    cudaGetSymbolAddress((void**)&p_c4,   g_coarse4);
    cudaGetSymbolAddress((void**)&p_tokf, g_tokfT);
    cudaGetSymbolAddress((void**)&p_outf, g_outfT);
    cudaGetSymbolAddress((void**)&p_t1,   g_t1);
    cudaGetSymbolAddress((void**)&p_b1s,  g_bn1sc);
    cudaGetSymbolAddress((void**)&p_b1h,  g_bn1sh);
    cudaGetSymbolAddress((void**)&p_b2s,  g_bn2sc);
    cudaGetSymbolAddress((void**)&p_b2h,  g_bn2sh);

    const float NEG = -3.0e38f, POS = 3.0e38f;

    k_bnprep<<<1, 256>>>(bn1_g, bn1_b, bn1_m, bn1_v, p_b1s, p_b1h);
    k_bnprep<<<1, 256>>>(bn2_g, bn2_b, bn2_m, bn2_v, p_b2s, p_b2h);
    k_wp<<<4096, 256>>>(up_w);

    // ---- down conv: im2col + GEMM -> xd
    k_im2col_down<<<131072, 256>>>(x);
    tg(0, down_w, p_col, p_xd, 256, 1024, 4096, 4096, 1024, 1024,
       0, 4096LL*1024, 256LL*1024, Bn, 1.f, nullptr, down_b, NEG, POS);

    // ---- coarse QKV
    tg(1, wqkv_c, p_xd, p_qc, 192, 1024, 64, 192, 1024, 1024,
       0, 65536, 192LL*1024, 32, 1.f, nullptr, bqkv_c, NEG, POS);

    // ---- coarse S = q^T k * scale
    tg(1, p_qc, p_qc + 65536, p_S, 1024, 1024, 64, 1024, 1024, 1024,
       196608, 196608, 1048576, 32, 0.125f, nullptr, nullptr, NEG, POS);
    k_softmax<<<32768, 256>>>(p_S);
    k_colsum<<<128, 256>>>(p_S);
    k_topk<<<32, 512>>>();

    // ---- coarse out: outc = vT @ P^T
    tg(2, p_qc + 131072, p_S, p_outc, 64, 1024, 1024, 1024, 1024, 1024,
       196608, 1048576, 65536, 32, 1.f, nullptr, nullptr, NEG, POS);

    // ---- up conv transpose: 4 parity GEMMs then interleave
    k_im2col_up<<<131072, 256>>>();
    for (int par = 0; par < 4; par++) {
        tg(0, p_Wp + (long long)par*262144, p_col + (long long)par*1048576,
           p_c4 + (long long)par*262144, 256, 1024, 1024, 1024, 1024, 1024,
           0, 4194304, 1048576, Bn, 1.f, nullptr, up_b, NEG, POS);
    }
    k_interleave<<<32768, 256>>>();

    // ---- fine attention
    k_gather_fine<<<8192, 256>>>();
    tg(1, wqkv_f, p_tokf, p_qf, 192, 1024, 64, 192, 1024, 1024,
       0, 65536, 192LL*1024, 32, 1.f, nullptr, bqkv_f, NEG, POS);
    tg(1, p_qf, p_qf + 65536, p_S, 1024, 1024, 64, 1024, 1024, 1024,
       196608, 196608, 1048576, 32, 0.125f, nullptr, nullptr, NEG, POS);
    k_softmax<<<32768, 256>>>(p_S);
    tg(2, p_qf + 131072, p_S, p_outf, 64, 1024, 1024, 1024, 1024, 1024,
       196608, 1048576, 65536, 32, 1.f, nullptr, nullptr, NEG, POS);

    // ---- residual combine
    k_copy<<<32768, 256>>>();
    k_scatter<<<8192, 256>>>();

    // ---- depthwise 3x3 + BN1 + relu6
    k_dw<<<32768, 256>>>(dw_w);

    // ---- pointwise 1x1 + BN2 + relu6 -> out
    tg(0, pw_w, p_t1, out, 256, 4096, 256, 256, 4096, 4096,
       0, 1048576, 1048576, Bn, 1.f, p_b2s, p_b2h, 0.f, 6.f);
}

// round 4
// speedup vs baseline: 2.1074x; 1.1134x over previous
#include <cuda_runtime.h>
#include <cuda_bf16.h>
#include <math.h>
#include <stdint.h>

#define Bn 8
#define Cn 256
#define Hn 64
#define Wn 64
#define NHn 4
#define HDn 64
#define NTOK 1024
#define KFn 256

// ---------------- static scratch ----------------
__device__ float g_xd[Bn*Cn*1024];
__device__ float g_qkvT_c[Bn*NHn*192*NTOK];
__device__ float g_qkvT_f[Bn*NHn*192*NTOK];
__device__ float g_S[Bn*NHn*NTOK*NTOK];
__device__ float g_score[Bn*NHn*NTOK];
__device__ int   g_topk[Bn*NHn*KFn];
__device__ float g_outc[Bn*Cn*1024];
__device__ float g_col[Bn*4096*1024];
__device__ float g_Wp[4*Cn*1024];
__device__ float g_coarse4[Bn*4*Cn*1024];
__device__ float g_coarse[Bn*Cn*Hn*Wn];
__device__ float g_tokfT[Bn*NHn*HDn*NTOK];
__device__ float g_outfT[Bn*NHn*HDn*NTOK];
__device__ float g_y0[Bn*Cn*Hn*Wn];
__device__ float g_t1[Bn*Cn*Hn*Wn];
__device__ float g_bn1sc[Cn], g_bn1sh[Cn], g_bn2sc[Cn], g_bn2sh[Cn];

// ================= HMMA helpers =================
__device__ __forceinline__ void ldsm4(uint32_t* r, uint32_t addr) {
    asm volatile("ldmatrix.sync.aligned.m8n8.x4.shared.b16 {%0,%1,%2,%3}, [%4];"
                 : "=r"(r[0]), "=r"(r[1]), "=r"(r[2]), "=r"(r[3]) : "r"(addr));
}
__device__ __forceinline__ void ldsm4t(uint32_t* r, uint32_t addr) {
    asm volatile("ldmatrix.sync.aligned.m8n8.x4.trans.shared.b16 {%0,%1,%2,%3}, [%4];"
                 : "=r"(r[0]), "=r"(r[1]), "=r"(r[2]), "=r"(r[3]) : "r"(addr));
}
__device__ __forceinline__ void mma16816(float* d, const uint32_t* a, const uint32_t* b) {
    asm volatile("mma.sync.aligned.m16n8k16.row.col.f32.bf16.bf16.f32 "
                 "{%0,%1,%2,%3},{%4,%5,%6,%7},{%8,%9},{%0,%1,%2,%3};"
                 : "+f"(d[0]), "+f"(d[1]), "+f"(d[2]), "+f"(d[3])
                 : "r"(a[0]), "r"(a[1]), "r"(a[2]), "r"(a[3]), "r"(b[0]), "r"(b[1]));
}

__device__ __forceinline__ uint32_t packbf2(float a, float b) {
    __nv_bfloat162 t;
    t.x = __float2bfloat16_rn(a);
    t.y = __float2bfloat16_rn(b);
    return *(uint32_t*)&t;
}

__device__ __forceinline__ void cvt4(char* base, uint32_t off, float4 f) {
    // hi 8B at base+off, lo 8B at base+off+10240 (off is 8B aligned)
    float hx = __bfloat162float(__float2bfloat16_rn(f.x));
    float hy = __bfloat162float(__float2bfloat16_rn(f.y));
    float hz = __bfloat162float(__float2bfloat16_rn(f.z));
    float hw = __bfloat162float(__float2bfloat16_rn(f.w));
    uint2 hv, lv;
    hv.x = packbf2(f.x, f.y);          hv.y = packbf2(f.z, f.w);
    lv.x = packbf2(f.x - hx, f.y - hy); lv.y = packbf2(f.z - hz, f.w - hw);
    *(uint2*)(base + off)         = hv;
    *(uint2*)(base + off + 10240) = lv;
}
__device__ __forceinline__ void cvt1(char* base, uint32_t off, float a) {
    __nv_bfloat16 h = __float2bfloat16_rn(a);
    __nv_bfloat16 l = __float2bfloat16_rn(a - __bfloat162float(h));
    *(__nv_bfloat16*)(base + off)         = h;
    *(__nv_bfloat16*)(base + off + 10240) = l;
}

// ================= tensor-core (HMMA) GEMM =================
#define SLOT 10240
#define STAGE (4*SLOT)
#define SMEM_HG (2*STAGE)

template<bool ATR, bool BKN>
__global__ __launch_bounds__(256) void hgemm(
    const float* __restrict__ A, const float* __restrict__ B, float* __restrict__ C,
    int M, int N, int K, int lda, int ldb, int ldc,
    long long sA, long long sB, long long sC,
    float alpha, const float* __restrict__ rowScale, const float* __restrict__ rowShift,
    float lo, float hi)
{
    extern __shared__ char sm[];
    const uint32_t smb = (uint32_t)__cvta_generic_to_shared(sm);
    const int tid = threadIdx.x;
    const int wid = tid >> 5, lane = tid & 31;
    const int grp = lane >> 2, tig = lane & 3;
    const int z = blockIdx.z;
    A += z * sA; B += z * sB; C += z * sC;
    const int m0 = blockIdx.y * 128, n0 = blockIdx.x * 128;
    const int mw = wid >> 1, nw = wid & 1;   // warp tile: 32m x 64n

    float acc[2][8][4];
    #pragma unroll
    for (int i = 0; i < 2; i++)
        #pragma unroll
        for (int j = 0; j < 8; j++)
            #pragma unroll
            for (int q = 0; q < 4; q++) acc[i][j][q] = 0.f;

    const int nch = K >> 5;
    float preA[16];
    float4 preB[4];

    auto load_regs = [&](int c) {
        const int k0c = c << 5;
        if (!ATR) {
            #pragma unroll
            for (int p = 0; p < 4; p++) {
                int m = (tid >> 3) + (p << 5);
                int mg = min(m0 + m, M - 1);
                *(float4*)(preA + p * 4) = *(const float4*)(A + (size_t)mg * lda + k0c + ((tid & 7) << 2));
            }
        } else {
            #pragma unroll
            for (int p = 0; p < 4; p++) {
                int k = (tid >> 5) + (p << 3);
                #pragma unroll
                for (int j = 0; j < 4; j++) {
                    int mg = min(m0 + ((tid & 31) << 2) + j, M - 1);
                    preA[p * 4 + j] = A[(size_t)(k0c + k) * lda + mg];
                }
            }
        }
        if (BKN) {
            #pragma unroll
            for (int p = 0; p < 4; p++) {
                int k = (tid >> 5) + (p << 3);
                preB[p] = *(const float4*)(B + (size_t)(k0c + k) * ldb + n0 + ((tid & 31) << 2));
            }
        } else {
            #pragma unroll
            for (int p = 0; p < 4; p++) {
                int n = (tid >> 3) + (p << 5);
                preB[p] = *(const float4*)(B + (size_t)(n0 + n) * ldb + k0c + ((tid & 7) << 2));
            }
        }
    };
    auto store_regs = [&](int s) {
        char* Abase = sm + s * STAGE;
        char* Bbase = Abase + 2 * SLOT;
        if (!ATR) {
            #pragma unroll
            for (int p = 0; p < 4; p++) {
                int m = (tid >> 3) + (p << 5);
                cvt4(Abase, (uint32_t)(m * 80 + ((tid & 7) << 3)), *(float4*)(preA + p * 4));
            }
        } else {
            #pragma unroll
            for (int p = 0; p < 4; p++) {
                int k = (tid >> 5) + (p << 3);
                #pragma unroll
                for (int j = 0; j < 4; j++)
                    cvt1(Abase, (uint32_t)(k * 272 + ((((tid & 31) << 2) + j) << 1)), preA[p * 4 + j]);
            }
        }
        if (BKN) {
            #pragma unroll
            for (int p = 0; p < 4; p++) {
                int k = (tid >> 5) + (p << 3);
                cvt4(Bbase, (uint32_t)(k * 272 + ((tid & 31) << 3)), preB[p]);
            }
        } else {
            #pragma unroll
            for (int p = 0; p < 4; p++) {
                int n = (tid >> 3) + (p << 5);
                cvt4(Bbase, (uint32_t)(n * 80 + ((tid & 7) << 3)), preB[p]);
            }
        }
    };
    auto compute = [&](int s) {
        const uint32_t Ab = smb + s * STAGE;
        const uint32_t Bb = Ab + 2 * SLOT;
        const int i = lane >> 3;
        #pragma unroll
        for (int kk = 0; kk < 32; kk += 16) {
            uint32_t ah[2][4], al[2][4];
            #pragma unroll
            for (int mf = 0; mf < 2; mf++) {
                uint32_t addr;
                if (!ATR) {
                    addr = Ab + (uint32_t)((mw * 32 + mf * 16 + (lane & 15)) * 80 + (kk + (lane >> 4) * 8) * 2);
                    ldsm4(ah[mf], addr); ldsm4(al[mf], addr + SLOT);
                } else {
                    addr = Ab + (uint32_t)((kk + (i >> 1) * 8 + (lane & 7)) * 272 + (mw * 32 + mf * 16 + (i & 1) * 8) * 2);
                    ldsm4t(ah[mf], addr); ldsm4t(al[mf], addr + SLOT);
                }
            }
            uint32_t bh[4][4], bl[4][4];
            #pragma unroll
            for (int nfp = 0; nfp < 4; nfp++) {
                uint32_t addr;
                if (BKN) {
                    addr = Bb + (uint32_t)((kk + (i & 1) * 8 + (lane & 7)) * 272 + (nw * 64 + nfp * 16 + (i >> 1) * 8) * 2);
                    ldsm4t(bh[nfp], addr); ldsm4t(bl[nfp], addr + SLOT);
                } else {
                    addr = Bb + (uint32_t)((nw * 64 + nfp * 16 + (i >> 1) * 8 + (lane & 7)) * 80 + (kk + (i & 1) * 8) * 2);
                    ldsm4(bh[nfp], addr); ldsm4(bl[nfp], addr + SLOT);
                }
            }
            // 3 passes (hh, hl, lh), 16 independent accumulators between reuses
            #pragma unroll
            for (int pass = 0; pass < 3; pass++) {
                #pragma unroll
                for (int nfp = 0; nfp < 4; nfp++) {
                    #pragma unroll
                    for (int mf = 0; mf < 2; mf++) {
                        #pragma unroll
                        for (int h = 0; h < 2; h++) {
                            const uint32_t* a = (pass == 2) ? al[mf] : ah[mf];
                            const uint32_t* b = ((pass == 1) ? bl[nfp] : bh[nfp]) + h * 2;
                            mma16816(acc[mf][nfp * 2 + h], a, b);
                        }
                    }
                }
            }
        }
    };

    load_regs(0);
    store_regs(0);
    __syncthreads();
    for (int c = 0; c < nch; c++) {
        const bool hasNext = (c + 1) < nch;
        if (hasNext) load_regs(c + 1);
        compute(c & 1);
        if (hasNext) store_regs((c + 1) & 1);
        __syncthreads();
    }

    // ---- epilogue ----
    float* stg = (float*)sm;   // [128][132]
    #pragma unroll
    for (int mf = 0; mf < 2; mf++) {
        int r0 = mw * 32 + mf * 16 + grp;
        int mg0 = min(m0 + r0, M - 1), mg1 = min(m0 + r0 + 8, M - 1);
        float av0 = alpha, av1 = alpha, sh0 = 0.f, sh1 = 0.f;
        if (rowScale) { av0 *= rowScale[mg0]; av1 *= rowScale[mg1]; }
        if (rowShift) { sh0 = rowShift[mg0]; sh1 = rowShift[mg1]; }
        #pragma unroll
        for (int nf = 0; nf < 8; nf++) {
            int cb = nw * 64 + nf * 8 + tig * 2;
            float* d = acc[mf][nf];
            stg[r0 * 132 + cb]           = fminf(fmaxf(d[0] * av0 + sh0, lo), hi);
            stg[r0 * 132 + cb + 1]       = fminf(fmaxf(d[1] * av0 + sh0, lo), hi);
            stg[(r0 + 8) * 132 + cb]     = fminf(fmaxf(d[2] * av1 + sh1, lo), hi);
            stg[(r0 + 8) * 132 + cb + 1] = fminf(fmaxf(d[3] * av1 + sh1, lo), hi);
        }
    }
    __syncthreads();
    #pragma unroll
    for (int it = 0; it < 16; it++) {
        int lin = tid + (it << 8);
        int rr = lin >> 5, c4 = (lin & 31) << 2;
        if (m0 + rr < M)
            *(float4*)(C + (size_t)(m0 + rr) * ldc + n0 + c4) = *(float4*)&stg[rr * 132 + c4];
    }
}

// ---------------- elementwise / helper kernels ----------------
__global__ void k_bnprep(const float* __restrict__ g, const float* __restrict__ b,
                         const float* __restrict__ m, const float* __restrict__ v,
                         float* __restrict__ sc, float* __restrict__ sh) {
    int i = threadIdx.x;
    if (i < Cn) {
        float inv = g[i] / sqrtf(v[i] + 1e-5f);
        sc[i] = inv;
        sh[i] = b[i] - m[i] * inv;
    }
}

// 4 outputs (consecutive ow) per thread
__global__ void k_im2col_down(const float* __restrict__ x) {
    int idx = blockIdx.x * 256 + threadIdx.x;     // Bn*4096*256
    int q  = idx & 255;                            // n/4
    int k  = (idx >> 8) & 4095;
    int b  = idx >> 20;
    int kw = k & 3, kh = (k >> 2) & 3, ci = k >> 4;
    int ow0 = (q & 7) << 2, oh = q >> 3;
    int ih = oh*2 - 1 + kh;
    const float* xr = x + ((long long)b*Cn + ci)*(Hn*Wn) + ih*Wn;
    float4 r;
    float* rp = (float*)&r;
    #pragma unroll
    for (int j = 0; j < 4; j++) {
        int iw = (ow0 + j)*2 - 1 + kw;
        rp[j] = (ih >= 0 && ih < Hn && iw >= 0 && iw < Wn) ? xr[iw] : 0.f;
    }
    *(float4*)&g_col[((long long)idx) << 2] = r;
}

__global__ void k_wp(const float* __restrict__ up_w) {
    int idx = blockIdx.x * 256 + threadIdx.x;
    if (idx >= 4*Cn*1024) return;
    int k = idx & 1023, co = (idx >> 10) & 255, p = idx >> 18;
    int tj = k & 1, ti = (k >> 1) & 1, ci = k >> 2;
    int px = p & 1, py = p >> 1;
    int kh = (py == 0) ? (ti == 0 ? 1 : 3) : (ti == 0 ? 0 : 2);
    int kw = (px == 0) ? (tj == 0 ? 1 : 3) : (tj == 0 ? 0 : 2);
    g_Wp[idx] = up_w[((ci << 8) + co) * 16 + kh*4 + kw];
}

// 4 outputs (consecutive c) per thread
__global__ void k_im2col_up() {
    int idx = blockIdx.x * 256 + threadIdx.x;     // 32*1024*256
    int q = idx & 255;
    int k = (idx >> 8) & 1023;
    int s = idx >> 18;
    int tj = k & 1, ti = (k >> 1) & 1, ci = k >> 2;
    int px = s & 1, py = (s >> 1) & 1, b = s >> 2;
    int c0 = (q & 7) << 2, a = q >> 3;
    int iy = (py == 0) ? (ti == 0 ? a : a - 1) : (ti == 0 ? a + 1 : a);
    int dx = (px == 0) ? (tj == 0 ? 0 : -1) : (tj == 0 ? 1 : 0);
    const float* orow = g_outc + ((long long)b*Cn + ci)*1024 + iy*32;
    float4 r;
    float* rp = (float*)&r;
    bool rowok = (iy >= 0 && iy < 32);
    #pragma unroll
    for (int j = 0; j < 4; j++) {
        int ix = c0 + j + dx;
        rp[j] = (rowok && ix >= 0 && ix < 32) ? orow[ix] : 0.f;
    }
    *(float4*)&g_col[((long long)idx) << 2] = r;
}

// interleave + copy fused: writes g_coarse and g_y0
__global__ void k_interleave() {
    int idx = blockIdx.x * 256 + threadIdx.x;     // 2^23
    int n = idx & 1023, co = (idx >> 10) & 255, s = idx >> 18;
    int px = s & 1, py = (s >> 1) & 1, b = s >> 2;
    int c = n & 31, a = n >> 5;
    float v = g_coarse4[idx];
    long long o = ((long long)b*Cn + co)*4096 + (2*a + py)*64 + (2*c + px);
    g_coarse[o] = v;
    g_y0[o] = v;
}

__global__ __launch_bounds__(256) void k_softmax(float* __restrict__ P) {
    __shared__ float red[8];
    long long row = blockIdx.x;
    float* p = P + row * 1024;
    int tid = threadIdx.x;
    float4 v = ((float4*)p)[tid];
    float mx = fmaxf(fmaxf(v.x, v.y), fmaxf(v.z, v.w));
    #pragma unroll
    for (int o = 16; o; o >>= 1) mx = fmaxf(mx, __shfl_xor_sync(0xffffffffu, mx, o));
    if ((tid & 31) == 0) red[tid >> 5] = mx;
    __syncthreads();
    if (tid == 0) {
        float m = red[0];
        #pragma unroll
        for (int i = 1; i < 8; i++) m = fmaxf(m, red[i]);
        red[0] = m;
    }
    __syncthreads();
    mx = red[0];
    __syncthreads();
    float e0 = __expf(v.x - mx), e1 = __expf(v.y - mx);
    float e2 = __expf(v.z - mx), e3 = __expf(v.w - mx);
    float s = (e0 + e1) + (e2 + e3);
    #pragma unroll
    for (int o = 16; o; o >>= 1) s += __shfl_xor_sync(0xffffffffu, s, o);
    if ((tid & 31) == 0) red[tid >> 5] = s;
    __syncthreads();
    if (tid == 0) {
        float t = 0.f;
        #pragma unroll
        for (int i = 0; i < 8; i++) t += red[i];
        red[0] = t;
    }
    __syncthreads();
    float inv = 1.f / red[0];
    v.x = e0 * inv; v.y = e1 * inv; v.z = e2 * inv; v.w = e3 * inv;
    ((float4*)p)[tid] = v;
}

__global__ void k_colsum(const float* __restrict__ P) {
    int z = blockIdx.x >> 2;
    int m = ((blockIdx.x & 3) << 8) + threadIdx.x;
    const float* p = P + (long long)z * 1048576 + m;
    float s = 0.f;
    #pragma unroll 8
    for (int n = 0; n < 1024; n++) s += p[(long long)n << 10];
    g_score[z * 1024 + m] = s;
}

__global__ __launch_bounds__(512) void k_topk() {
    __shared__ float v[1024];
    __shared__ int   ix[1024];
    int z = blockIdx.x, tid = threadIdx.x;
    for (int i = tid; i < 1024; i += 512) { v[i] = g_score[z*1024 + i]; ix[i] = i; }
    __syncthreads();
    for (int k = 2; k <= 1024; k <<= 1) {
        for (int j = k >> 1; j > 0; j >>= 1) {
            for (int i = tid; i < 1024; i += 512) {
                int l = i ^ j;
                if (l > i) {
                    bool up = ((i & k) == 0);
                    bool sw = up ? (v[i] < v[l]) : (v[i] > v[l]);
                    if (sw) {
                        float tv = v[i]; v[i] = v[l]; v[l] = tv;
                        int ti2 = ix[i]; ix[i] = ix[l]; ix[l] = ti2;
                    }
                }
            }
            __syncthreads();
        }
    }
    for (int i = tid; i < KFn; i += 512) g_topk[z*KFn + i] = ix[i];
}

__global__ void k_gather_fine() {
    int idx = blockIdx.x * 256 + threadIdx.x;
    int t = idx & 1023, d = (idx >> 10) & 63, z = idx >> 16;
    int ki = t >> 2, i = (t >> 1) & 1, j = t & 1;
    int p = g_topk[(z << 8) + ki];
    int pi = p >> 5, pj = p & 31;
    int b = z >> 2, h = z & 3;
    g_tokfT[idx] = g_coarse[((long long)b*Cn + (h*HDn + d))*4096 + (2*pi + i)*64 + (2*pj + j)];
}

__global__ void k_scatter() {
    int idx = blockIdx.x * 256 + threadIdx.x;
    int t = idx & 1023, d = (idx >> 10) & 63, z = idx >> 16;
    int ki = t >> 2, i = (t >> 1) & 1, j = t & 1;
    int p = g_topk[(z << 8) + ki];
    int pi = p >> 5, pj = p & 31;
    int b = z >> 2, h = z & 3;
    g_y0[((long long)b*Cn + (h*HDn + d))*4096 + (2*pi + i)*64 + (2*pj + j)] += g_outfT[idx];
}

// depthwise 3x3 + BN1 + relu6 : 4 outputs per thread
__global__ void k_dw(const float* __restrict__ dw_w) {
    int idx = blockIdx.x * 256 + threadIdx.x;      // 2^21
    int x4 = (idx & 15) << 2, y = (idx >> 4) & 63, c = (idx >> 10) & 255, b = idx >> 18;
    const float* base = g_y0 + ((long long)b*Cn + c)*4096;
    const float* wp = dw_w + c*9;
    float s[4] = {0.f, 0.f, 0.f, 0.f};
    #pragma unroll
    for (int ky = 0; ky < 3; ky++) {
        int yy = y + ky - 1;
        if (yy < 0 || yy >= 64) continue;
        const float* row = base + yy*64;
        float4 mid = *(const float4*)(row + x4);
        float lft = (x4 > 0)  ? row[x4 - 1] : 0.f;
        float rgt = (x4 < 60) ? row[x4 + 4] : 0.f;
        float w0 = wp[ky*3], w1 = wp[ky*3 + 1], w2 = wp[ky*3 + 2];
        s[0] = fmaf(lft,   w0, fmaf(mid.x, w1, fmaf(mid.y, w2, s[0])));
        s[1] = fmaf(mid.x, w0, fmaf(mid.y, w1, fmaf(mid.z, w2, s[1])));
        s[2] = fmaf(mid.y, w0, fmaf(mid.z, w1, fmaf(mid.w, w2, s[2])));
        s[3] = fmaf(mid.z, w0, fmaf(mid.w, w1, fmaf(rgt,   w2, s[3])));
    }
    float sc = g_bn1sc[c], sh = g_bn1sh[c];
    float4 r;
    r.x = fminf(fmaxf(s[0]*sc + sh, 0.f), 6.f);
    r.y = fminf(fmaxf(s[1]*sc + sh, 0.f), 6.f);
    r.z = fminf(fmaxf(s[2]*sc + sh, 0.f), 6.f);
    r.w = fminf(fmaxf(s[3]*sc + sh, 0.f), 6.f);
    *(float4*)&g_t1[((long long)b*Cn + c)*4096 + y*64 + x4] = r;
}

// ---------------- host ----------------
static void tg(int mode, const float* A, const float* B, float* Cc,
               int M, int N, int K, int lda, int ldb, int ldc,
               long long sA, long long sB, long long sC, int Z,
               float alpha, const float* sc, const float* sh, float lo, float hi)
{
    dim3 grid(N / 128, (M + 127) / 128, Z), blk(256);
    size_t shm = SMEM_HG;
    if (mode == 0) {
        cudaFuncSetAttribute(hgemm<false,true>, cudaFuncAttributeMaxDynamicSharedMemorySize, (int)shm);
        hgemm<false,true><<<grid, blk, shm>>>(A, B, Cc, M, N, K, lda, ldb, ldc, sA, sB, sC, alpha, sc, sh, lo, hi);
    } else if (mode == 1) {
        cudaFuncSetAttribute(hgemm<true,true>, cudaFuncAttributeMaxDynamicSharedMemorySize, (int)shm);
        hgemm<true,true><<<grid, blk, shm>>>(A, B, Cc, M, N, K, lda, ldb, ldc, sA, sB, sC, alpha, sc, sh, lo, hi);
    } else {
        cudaFuncSetAttribute(hgemm<false,false>, cudaFuncAttributeMaxDynamicSharedMemorySize, (int)shm);
        hgemm<false,false><<<grid, blk, shm>>>(A, B, Cc, M, N, K, lda, ldb, ldc, sA, sB, sC, alpha, sc, sh, lo, hi);
    }
}

extern "C" void kernel_launch(void* const* d_in, const int* in_sizes, int n_in,
                              void* d_out, int out_size)
{
    const float* x      = (const float*)d_in[0];
    const float* down_w = (const float*)d_in[1];
    const float* down_b = (const float*)d_in[2];
    const float* up_w   = (const float*)d_in[3];
    const float* up_b   = (const float*)d_in[4];
    const float* wqkv_c = (const float*)d_in[5];
    const float* bqkv_c = (const float*)d_in[6];
    const float* wqkv_f = (const float*)d_in[7];
    const float* bqkv_f = (const float*)d_in[8];
    const float* dw_w   = (const float*)d_in[9];
    const float* bn1_g  = (const float*)d_in[10];
    const float* bn1_b  = (const float*)d_in[11];
    const float* bn1_m  = (const float*)d_in[12];
    const float* bn1_v  = (const float*)d_in[13];
    const float* pw_w   = (const float*)d_in[14];
    const float* bn2_g  = (const float*)d_in[15];
    const float* bn2_b  = (const float*)d_in[16];
    const float* bn2_m  = (const float*)d_in[17];
    const float* bn2_v  = (const float*)d_in[18];
    float* out = (float*)d_out;

    float *p_xd, *p_qc, *p_qf, *p_S, *p_outc, *p_col, *p_Wp, *p_c4, *p_tokf, *p_outf, *p_t1;
    float *p_b1s, *p_b1h, *p_b2s, *p_b2h;
    cudaGetSymbolAddress((void**)&p_xd,   g_xd);
    cudaGetSymbolAddress((void**)&p_qc,   g_qkvT_c);
    cudaGetSymbolAddress((void**)&p_qf,   g_qkvT_f);
    cudaGetSymbolAddress((void**)&p_S,    g_S);
    cudaGetSymbolAddress((void**)&p_outc, g_outc);
    cudaGetSymbolAddress((void**)&p_col,  g_col);
    cudaGetSymbolAddress((void**)&p_Wp,   g_Wp);
    cudaGetSymbolAddress((void**)&p_c4,   g_coarse4);
    cudaGetSymbolAddress((void**)&p_tokf, g_tokfT);
    cudaGetSymbolAddress((void**)&p_outf, g_outfT);
    cudaGetSymbolAddress((void**)&p_t1,   g_t1);
    cudaGetSymbolAddress((void**)&p_b1s,  g_bn1sc);
    cudaGetSymbolAddress((void**)&p_b1h,  g_bn1sh);
    cudaGetSymbolAddress((void**)&p_b2s,  g_bn2sc);
    cudaGetSymbolAddress((void**)&p_b2h,  g_bn2sh);

    const float NEG = -3.0e38f, POS = 3.0e38f;

    k_bnprep<<<1, 256>>>(bn1_g, bn1_b, bn1_m, bn1_v, p_b1s, p_b1h);
    k_bnprep<<<1, 256>>>(bn2_g, bn2_b, bn2_m, bn2_v, p_b2s, p_b2h);
    k_wp<<<4096, 256>>>(up_w);

    // ---- down conv: im2col + GEMM -> xd
    k_im2col_down<<<32768, 256>>>(x);
    tg(0, down_w, p_col, p_xd, 256, 1024, 4096, 4096, 1024, 1024,
       0, 4096LL*1024, 256LL*1024, Bn, 1.f, nullptr, down_b, NEG, POS);

    // ---- coarse QKV
    tg(1, wqkv_c, p_xd, p_qc, 192, 1024, 64, 192, 1024, 1024,
       0, 65536, 192LL*1024, 32, 1.f, nullptr, bqkv_c, NEG, POS);

    // ---- coarse S = q^T k * scale
    tg(1, p_qc, p_qc + 65536, p_S, 1024, 1024, 64, 1024, 1024, 1024,
       196608, 196608, 1048576, 32, 0.125f, nullptr, nullptr, NEG, POS);
    k_softmax<<<32768, 256>>>(p_S);
    k_colsum<<<128, 256>>>(p_S);
    k_topk<<<32, 512>>>();

    // ---- coarse out: outc = vT @ P^T
    tg(2, p_qc + 131072, p_S, p_outc, 64, 1024, 1024, 1024, 1024, 1024,
       196608, 1048576, 65536, 32, 1.f, nullptr, nullptr, NEG, POS);

    // ---- up conv transpose: 4 parity GEMMs then interleave(+copy)
    k_im2col_up<<<32768, 256>>>();
    for (int par = 0; par < 4; par++) {
        tg(0, p_Wp + (long long)par*262144, p_col + (long long)par*1048576,
           p_c4 + (long long)par*262144, 256, 1024, 1024, 1024, 1024, 1024,
           0, 4194304, 1048576, Bn, 1.f, nullptr, up_b, NEG, POS);
    }
    k_interleave<<<32768, 256>>>();

    // ---- fine attention
    k_gather_fine<<<8192, 256>>>();
    tg(1, wqkv_f, p_tokf, p_qf, 192, 1024, 64, 192, 1024, 1024,
       0, 65536, 192LL*1024, 32, 1.f, nullptr, bqkv_f, NEG, POS);
    tg(1, p_qf, p_qf + 65536, p_S, 1024, 1024, 64, 1024, 1024, 1024,
       196608, 196608, 1048576, 32, 0.125f, nullptr, nullptr, NEG, POS);
    k_softmax<<<32768, 256>>>(p_S);
    tg(2, p_qf + 131072, p_S, p_outf, 64, 1024, 1024, 1024, 1024, 1024,
       196608, 1048576, 65536, 32, 1.f, nullptr, nullptr, NEG, POS);

    // ---- residual add of fine output into y0 (y0 written by k_interleave)
    k_scatter<<<8192, 256>>>();

    // ---- depthwise 3x3 + BN1 + relu6
    k_dw<<<8192, 256>>>(dw_w);

    // ---- pointwise 1x1 + BN2 + relu6 -> out
    tg(0, pw_w, p_t1, out, 256, 4096, 256, 256, 4096, 4096,
       0, 1048576, 1048576, Bn, 1.f, p_b2s, p_b2h, 0.f, 6.f);
}

// round 5
// speedup vs baseline: 2.1455x; 1.0181x over previous
#include <cuda_runtime.h>
#include <cuda_bf16.h>
#include <math.h>
#include <stdint.h>

#define Bn 8
#define Cn 256
#define Hn 64
#define Wn 64
#define NHn 4
#define HDn 64
#define NTOK 1024
#define KFn 256

typedef __nv_bfloat16 bf;

// ---------------- static scratch ----------------
__device__ bf    g_colh[33554432], g_coll[33554432];     // im2col planes (down, then up)
__device__ bf    g_xdh[2097152],  g_xdl[2097152];        // down-conv out planes
__device__ bf    g_qch[6291456],  g_qcl[6291456];        // coarse qkvT planes [z][192][1024]
__device__ bf    g_qfh[6291456],  g_qfl[6291456];        // fine qkvT planes
__device__ float g_S[33554432];                          // attn logits fp32
__device__ bf    g_Ph[33554432],  g_Pl[33554432];        // attn prob planes
__device__ float g_score[Bn*NHn*NTOK];
__device__ int   g_topk[Bn*NHn*KFn];
__device__ float g_outc[Bn*Cn*1024];
__device__ bf    g_tokh[2097152], g_tokl[2097152];       // fine token planes
__device__ float g_outfT[2097152];
__device__ float g_coarse4[33554432];
__device__ float g_coarse[8388608];
__device__ float g_y0[8388608];
__device__ bf    g_t1h[8388608],  g_t1l[8388608];        // dw output planes
__device__ bf    g_wdh[1048576],  g_wdl[1048576];        // down_w planes [256][4096]
__device__ bf    g_Wph[1048576],  g_Wpl[1048576];        // up-conv parity weight planes
__device__ bf    g_wqch[12288],   g_wqcl[12288];         // wqkv_c^T planes [192][64]
__device__ bf    g_wqfh[12288],   g_wqfl[12288];
__device__ bf    g_pwh[65536],    g_pwl[65536];          // pw_w planes [256][256]
__device__ float g_bn1sc[Cn], g_bn1sh[Cn], g_bn2sc[Cn], g_bn2sh[Cn];

// ================= helpers =================
__device__ __forceinline__ void ldsm4(uint32_t* r, uint32_t addr) {
    asm volatile("ldmatrix.sync.aligned.m8n8.x4.shared.b16 {%0,%1,%2,%3}, [%4];"
                 : "=r"(r[0]), "=r"(r[1]), "=r"(r[2]), "=r"(r[3]) : "r"(addr));
}
__device__ __forceinline__ void ldsm4t(uint32_t* r, uint32_t addr) {
    asm volatile("ldmatrix.sync.aligned.m8n8.x4.trans.shared.b16 {%0,%1,%2,%3}, [%4];"
                 : "=r"(r[0]), "=r"(r[1]), "=r"(r[2]), "=r"(r[3]) : "r"(addr));
}
__device__ __forceinline__ void mma16816(float* d, const uint32_t* a, const uint32_t* b) {
    asm volatile("mma.sync.aligned.m16n8k16.row.col.f32.bf16.bf16.f32 "
                 "{%0,%1,%2,%3},{%4,%5,%6,%7},{%8,%9},{%0,%1,%2,%3};"
                 : "+f"(d[0]), "+f"(d[1]), "+f"(d[2]), "+f"(d[3])
                 : "r"(a[0]), "r"(a[1]), "r"(a[2]), "r"(a[3]), "r"(b[0]), "r"(b[1]));
}
__device__ __forceinline__ void cpa16(uint32_t dst, const void* src) {
    asm volatile("cp.async.cg.shared.global [%0], [%1], 16;" :: "r"(dst), "l"(src));
}
#define CP_COMMIT() asm volatile("cp.async.commit_group;" ::: "memory")
#define CP_WAIT0()  asm volatile("cp.async.wait_group 0;" ::: "memory")

__device__ __forceinline__ uint32_t packbf2(float a, float b) {
    __nv_bfloat162 t;
    t.x = __float2bfloat16_rn(a); t.y = __float2bfloat16_rn(b);
    return *(uint32_t*)&t;
}
// split 4 floats into hi/lo bf16x4 (uint2 each)
__device__ __forceinline__ void split4(float4 f, uint2& hv, uint2& lv) {
    float hx = __bfloat162float(__float2bfloat16_rn(f.x));
    float hy = __bfloat162float(__float2bfloat16_rn(f.y));
    float hz = __bfloat162float(__float2bfloat16_rn(f.z));
    float hw = __bfloat162float(__float2bfloat16_rn(f.w));
    hv.x = packbf2(f.x, f.y);           hv.y = packbf2(f.z, f.w);
    lv.x = packbf2(f.x - hx, f.y - hy); lv.y = packbf2(f.z - hz, f.w - hw);
}
__device__ __forceinline__ void split1(float a, bf* oh, bf* ol) {
    bf h = __float2bfloat16_rn(a);
    *oh = h;
    *ol = __float2bfloat16_rn(a - __bfloat162float(h));
}

// ================= cp.async bf16-plane HMMA GEMM =================
// C = clamp(alpha*rowScale[m]*sum_k A[m,k]*B[n,k] + rowShift[m], lo, hi)
// A/B given as hi/lo bf16 planes. ATR: A stored KxM; BKN: B stored KxN (else NxK).
// Output: fp32 (Cf) or bf16 planes (Ch/Cl).
#define SLOT 10240
#define STAGE (4*SLOT)
#define SMEM_HG (2*STAGE)

template<bool ATR, bool BKN>
__global__ __launch_bounds__(256) void hgemm(
    const bf* __restrict__ Agh, const bf* __restrict__ Agl,
    const bf* __restrict__ Bgh, const bf* __restrict__ Bgl,
    float* __restrict__ Cf, bf* __restrict__ Ch, bf* __restrict__ Cl,
    int M, int N, int K, int lda, int ldb, int ldc,
    long long sA, long long sB, long long sC,
    float alpha, const float* __restrict__ rowScale, const float* __restrict__ rowShift,
    float lo, float hi)
{
    extern __shared__ char sm[];
    const uint32_t smb = (uint32_t)__cvta_generic_to_shared(sm);
    const int tid = threadIdx.x;
    const int wid = tid >> 5, lane = tid & 31;
    const int grp = lane >> 2, tig = lane & 3;
    const int z = blockIdx.z;
    Agh += z * sA; Agl += z * sA; Bgh += z * sB; Bgl += z * sB;
    if (Cf) Cf += z * sC;
    if (Ch) { Ch += z * sC; Cl += z * sC; }
    const int m0 = blockIdx.y * 128, n0 = blockIdx.x * 128;
    const int mw = wid >> 1, nw = wid & 1;

    float acc[2][8][4];
    #pragma unroll
    for (int i = 0; i < 2; i++)
        #pragma unroll
        for (int j = 0; j < 8; j++)
            #pragma unroll
            for (int q = 0; q < 4; q++) acc[i][j][q] = 0.f;

    const int nch = K >> 5;

    auto stage_copy = [&](int c, int s) {
        const int k0 = c << 5;
        const uint32_t Ab = smb + s * STAGE;
        const uint32_t Bb = Ab + 2 * SLOT;
        #pragma unroll
        for (int p = 0; p < 2; p++) {
            int id = tid + (p << 8);
            if (!ATR) {
                int m = id >> 2, part = id & 3;
                int mg = min(m0 + m, M - 1);
                size_t off = (size_t)mg * lda + k0 + part * 8;
                uint32_t d = Ab + m * 80 + part * 16;
                cpa16(d, Agh + off);
                cpa16(d + SLOT, Agl + off);
            } else {
                int k = id >> 4, part = id & 15;
                size_t off = (size_t)(k0 + k) * lda + m0 + part * 8;
                uint32_t d = Ab + k * 272 + part * 16;
                cpa16(d, Agh + off);
                cpa16(d + SLOT, Agl + off);
            }
        }
        #pragma unroll
        for (int p = 0; p < 2; p++) {
            int id = tid + (p << 8);
            if (BKN) {
                int k = id >> 4, part = id & 15;
                size_t off = (size_t)(k0 + k) * ldb + n0 + part * 8;
                uint32_t d = Bb + k * 272 + part * 16;
                cpa16(d, Bgh + off);
                cpa16(d + SLOT, Bgl + off);
            } else {
                int n = id >> 2, part = id & 3;
                size_t off = (size_t)(n0 + n) * ldb + k0 + part * 8;
                uint32_t d = Bb + n * 80 + part * 16;
                cpa16(d, Bgh + off);
                cpa16(d + SLOT, Bgl + off);
            }
        }
    };

    auto compute = [&](int s) {
        const uint32_t Ab = smb + s * STAGE;
        const uint32_t Bb = Ab + 2 * SLOT;
        const int i = lane >> 3;
        #pragma unroll
        for (int kk = 0; kk < 32; kk += 16) {
            uint32_t ah[2][4], al[2][4];
            #pragma unroll
            for (int mf = 0; mf < 2; mf++) {
                uint32_t addr;
                if (!ATR) {
                    addr = Ab + (uint32_t)((mw * 32 + mf * 16 + (lane & 15)) * 80 + (kk + (lane >> 4) * 8) * 2);
                    ldsm4(ah[mf], addr); ldsm4(al[mf], addr + SLOT);
                } else {
                    addr = Ab + (uint32_t)((kk + (i >> 1) * 8 + (lane & 7)) * 272 + (mw * 32 + mf * 16 + (i & 1) * 8) * 2);
                    ldsm4t(ah[mf], addr); ldsm4t(al[mf], addr + SLOT);
                }
            }
            uint32_t bh[4][4], bl[4][4];
            #pragma unroll
            for (int nfp = 0; nfp < 4; nfp++) {
                uint32_t addr;
                if (BKN) {
                    addr = Bb + (uint32_t)((kk + (i & 1) * 8 + (lane & 7)) * 272 + (nw * 64 + nfp * 16 + (i >> 1) * 8) * 2);
                    ldsm4t(bh[nfp], addr); ldsm4t(bl[nfp], addr + SLOT);
                } else {
                    addr = Bb + (uint32_t)((nw * 64 + nfp * 16 + (i >> 1) * 8 + (lane & 7)) * 80 + (kk + (i & 1) * 8) * 2);
                    ldsm4(bh[nfp], addr); ldsm4(bl[nfp], addr + SLOT);
                }
            }
            #pragma unroll
            for (int pass = 0; pass < 3; pass++) {
                #pragma unroll
                for (int nfp = 0; nfp < 4; nfp++) {
                    #pragma unroll
                    for (int mf = 0; mf < 2; mf++) {
                        #pragma unroll
                        for (int h = 0; h < 2; h++) {
                            const uint32_t* a = (pass == 2) ? al[mf] : ah[mf];
                            const uint32_t* b = ((pass == 1) ? bl[nfp] : bh[nfp]) + h * 2;
                            mma16816(acc[mf][nfp * 2 + h], a, b);
                        }
                    }
                }
            }
        }
    };

    stage_copy(0, 0); CP_COMMIT();
    for (int c = 0; c < nch; c++) {
        CP_WAIT0();
        __syncthreads();
        if (c + 1 < nch) { stage_copy(c + 1, (c + 1) & 1); CP_COMMIT(); }
        compute(c & 1);
    }
    __syncthreads();

    // ---- epilogue: regs -> smem stage -> coalesced gmem ----
    float* stg = (float*)sm;   // [128][132]
    #pragma unroll
    for (int mf = 0; mf < 2; mf++) {
        int r0 = mw * 32 + mf * 16 + grp;
        int mg0 = min(m0 + r0, M - 1), mg1 = min(m0 + r0 + 8, M - 1);
        float av0 = alpha, av1 = alpha, sh0 = 0.f, sh1 = 0.f;
        if (rowScale) { av0 *= rowScale[mg0]; av1 *= rowScale[mg1]; }
        if (rowShift) { sh0 = rowShift[mg0]; sh1 = rowShift[mg1]; }
        #pragma unroll
        for (int nf = 0; nf < 8; nf++) {
            int cb = nw * 64 + nf * 8 + tig * 2;
            float* d = acc[mf][nf];
            stg[r0 * 132 + cb]           = fminf(fmaxf(d[0] * av0 + sh0, lo), hi);
            stg[r0 * 132 + cb + 1]       = fminf(fmaxf(d[1] * av0 + sh0, lo), hi);
            stg[(r0 + 8) * 132 + cb]     = fminf(fmaxf(d[2] * av1 + sh1, lo), hi);
            stg[(r0 + 8) * 132 + cb + 1] = fminf(fmaxf(d[3] * av1 + sh1, lo), hi);
        }
    }
    __syncthreads();
    if (Cf) {
        #pragma unroll
        for (int it = 0; it < 16; it++) {
            int lin = tid + (it << 8);
            int rr = lin >> 5, c4 = (lin & 31) << 2;
            if (m0 + rr < M)
                *(float4*)(Cf + (size_t)(m0 + rr) * ldc + n0 + c4) = *(float4*)&stg[rr * 132 + c4];
        }
    } else {
        #pragma unroll
        for (int it = 0; it < 16; it++) {
            int lin = tid + (it << 8);
            int rr = lin >> 5, c4 = (lin & 31) << 2;
            if (m0 + rr < M) {
                float4 v = *(float4*)&stg[rr * 132 + c4];
                uint2 hv, lv;
                split4(v, hv, lv);
                size_t o = (size_t)(m0 + rr) * ldc + n0 + c4;
                *(uint2*)(Ch + o) = hv;
                *(uint2*)(Cl + o) = lv;
            }
        }
    }
}

// ---------------- elementwise / helper kernels ----------------
__global__ void k_bnprep(const float* __restrict__ g, const float* __restrict__ b,
                         const float* __restrict__ m, const float* __restrict__ v,
                         float* __restrict__ sc, float* __restrict__ sh) {
    int i = threadIdx.x;
    if (i < Cn) {
        float inv = g[i] / sqrtf(v[i] + 1e-5f);
        sc[i] = inv;
        sh[i] = b[i] - m[i] * inv;
    }
}

// generic fp32 -> bf16 hi/lo planes, optional transpose (src [K][M] -> out [M][K])
__global__ void k_prep(const float* __restrict__ src, bf* __restrict__ oh, bf* __restrict__ ol,
                       int Mh, int Kd, int trans) {
    int idx = blockIdx.x * 256 + threadIdx.x;
    if (idx >= Mh * Kd) return;
    int m = idx / Kd, k = idx % Kd;
    float v = trans ? src[(size_t)k * Mh + m] : src[idx];
    split1(v, oh + idx, ol + idx);
}

__global__ void k_im2col_down(const float* __restrict__ x) {
    int idx = blockIdx.x * 256 + threadIdx.x;     // Bn*4096*256
    int q  = idx & 255;
    int k  = (idx >> 8) & 4095;
    int b  = idx >> 20;
    int kw = k & 3, kh = (k >> 2) & 3, ci = k >> 4;
    int ow0 = (q & 7) << 2, oh = q >> 3;
    int ih = oh*2 - 1 + kh;
    const float* xr = x + ((long long)b*Cn + ci)*(Hn*Wn) + ih*Wn;
    float4 r;
    float* rp = (float*)&r;
    #pragma unroll
    for (int j = 0; j < 4; j++) {
        int iw = (ow0 + j)*2 - 1 + kw;
        rp[j] = (ih >= 0 && ih < Hn && iw >= 0 && iw < Wn) ? xr[iw] : 0.f;
    }
    uint2 hv, lv; split4(r, hv, lv);
    size_t o = ((size_t)idx) << 2;
    *(uint2*)&g_colh[o] = hv;
    *(uint2*)&g_coll[o] = lv;
}

__global__ void k_wp(const float* __restrict__ up_w) {
    int idx = blockIdx.x * 256 + threadIdx.x;
    if (idx >= 4*Cn*1024) return;
    int k = idx & 1023, co = (idx >> 10) & 255, p = idx >> 18;
    int tj = k & 1, ti = (k >> 1) & 1, ci = k >> 2;
    int px = p & 1, py = p >> 1;
    int kh = (py == 0) ? (ti == 0 ? 1 : 3) : (ti == 0 ? 0 : 2);
    int kw = (px == 0) ? (tj == 0 ? 1 : 3) : (tj == 0 ? 0 : 2);
    split1(up_w[((ci << 8) + co) * 16 + kh*4 + kw], g_Wph + idx, g_Wpl + idx);
}

__global__ void k_im2col_up() {
    int idx = blockIdx.x * 256 + threadIdx.x;     // 32*1024*256
    int q = idx & 255;
    int k = (idx >> 8) & 1023;
    int s = idx >> 18;
    int tj = k & 1, ti = (k >> 1) & 1, ci = k >> 2;
    int px = s & 1, py = (s >> 1) & 1, b = s >> 2;
    int c0 = (q & 7) << 2, a = q >> 3;
    int iy = (py == 0) ? (ti == 0 ? a : a - 1) : (ti == 0 ? a + 1 : a);
    int dx = (px == 0) ? (tj == 0 ? 0 : -1) : (tj == 0 ? 1 : 0);
    const float* orow = g_outc + ((long long)b*Cn + ci)*1024 + iy*32;
    float4 r;
    float* rp = (float*)&r;
    bool rowok = (iy >= 0 && iy < 32);
    #pragma unroll
    for (int j = 0; j < 4; j++) {
        int ix = c0 + j + dx;
        rp[j] = (rowok && ix >= 0 && ix < 32) ? orow[ix] : 0.f;
    }
    uint2 hv, lv; split4(r, hv, lv);
    size_t o = ((size_t)idx) << 2;
    *(uint2*)&g_colh[o] = hv;
    *(uint2*)&g_coll[o] = lv;
}

__global__ void k_interleave() {
    int idx = blockIdx.x * 256 + threadIdx.x;     // 2^23
    int n = idx & 1023, co = (idx >> 10) & 255, s = idx >> 18;
    int px = s & 1, py = (s >> 1) & 1, b = s >> 2;
    int c = n & 31, a = n >> 5;
    float v = g_coarse4[idx];
    long long o = ((long long)b*Cn + co)*4096 + (2*a + py)*64 + (2*c + px);
    g_coarse[o] = v;
    g_y0[o] = v;
}

// softmax: fp32 logits in, bf16 hi/lo prob planes out
__global__ __launch_bounds__(256) void k_softmax(const float* __restrict__ S,
                                                 bf* __restrict__ Ph, bf* __restrict__ Pl) {
    __shared__ float red[8];
    long long row = blockIdx.x;
    const float* p = S + row * 1024;
    int tid = threadIdx.x;
    float4 v = ((const float4*)p)[tid];
    float mx = fmaxf(fmaxf(v.x, v.y), fmaxf(v.z, v.w));
    #pragma unroll
    for (int o = 16; o; o >>= 1) mx = fmaxf(mx, __shfl_xor_sync(0xffffffffu, mx, o));
    if ((tid & 31) == 0) red[tid >> 5] = mx;
    __syncthreads();
    if (tid == 0) {
        float m = red[0];
        #pragma unroll
        for (int i = 1; i < 8; i++) m = fmaxf(m, red[i]);
        red[0] = m;
    }
    __syncthreads();
    mx = red[0];
    __syncthreads();
    float e0 = __expf(v.x - mx), e1 = __expf(v.y - mx);
    float e2 = __expf(v.z - mx), e3 = __expf(v.w - mx);
    float s = (e0 + e1) + (e2 + e3);
    #pragma unroll
    for (int o = 16; o; o >>= 1) s += __shfl_xor_sync(0xffffffffu, s, o);
    if ((tid & 31) == 0) red[tid >> 5] = s;
    __syncthreads();
    if (tid == 0) {
        float t = 0.f;
        #pragma unroll
        for (int i = 0; i < 8; i++) t += red[i];
        red[0] = t;
    }
    __syncthreads();
    float inv = 1.f / red[0];
    float4 r;
    r.x = e0 * inv; r.y = e1 * inv; r.z = e2 * inv; r.w = e3 * inv;
    uint2 hv, lv; split4(r, hv, lv);
    size_t o = row * 1024 + (size_t)tid * 4;
    *(uint2*)(Ph + o) = hv;
    *(uint2*)(Pl + o) = lv;
}

__global__ void k_colsum() {
    int z = blockIdx.x >> 2;
    int m = ((blockIdx.x & 3) << 8) + threadIdx.x;
    const bf* ph = g_Ph + (long long)z * 1048576 + m;
    const bf* pl = g_Pl + (long long)z * 1048576 + m;
    float s = 0.f;
    #pragma unroll 8
    for (int n = 0; n < 1024; n++) {
        long long o = (long long)n << 10;
        s += __bfloat162float(ph[o]) + __bfloat162float(pl[o]);
    }
    g_score[z * 1024 + m] = s;
}

__global__ __launch_bounds__(512) void k_topk() {
    __shared__ float v[1024];
    __shared__ int   ix[1024];
    int z = blockIdx.x, tid = threadIdx.x;
    for (int i = tid; i < 1024; i += 512) { v[i] = g_score[z*1024 + i]; ix[i] = i; }
    __syncthreads();
    for (int k = 2; k <= 1024; k <<= 1) {
        for (int j = k >> 1; j > 0; j >>= 1) {
            for (int i = tid; i < 1024; i += 512) {
                int l = i ^ j;
                if (l > i) {
                    bool up = ((i & k) == 0);
                    bool sw = up ? (v[i] < v[l]) : (v[i] > v[l]);
                    if (sw) {
                        float tv = v[i]; v[i] = v[l]; v[l] = tv;
                        int ti2 = ix[i]; ix[i] = ix[l]; ix[l] = ti2;
                    }
                }
            }
            __syncthreads();
        }
    }
    for (int i = tid; i < KFn; i += 512) g_topk[z*KFn + i] = ix[i];
}

__global__ void k_gather_fine() {
    int idx = blockIdx.x * 256 + threadIdx.x;
    int t = idx & 1023, d = (idx >> 10) & 63, z = idx >> 16;
    int ki = t >> 2, i = (t >> 1) & 1, j = t & 1;
    int p = g_topk[(z << 8) + ki];
    int pi = p >> 5, pj = p & 31;
    int b = z >> 2, h = z & 3;
    float v = g_coarse[((long long)b*Cn + (h*HDn + d))*4096 + (2*pi + i)*64 + (2*pj + j)];
    split1(v, g_tokh + idx, g_tokl + idx);
}

__global__ void k_scatter() {
    int idx = blockIdx.x * 256 + threadIdx.x;
    int t = idx & 1023, d = (idx >> 10) & 63, z = idx >> 16;
    int ki = t >> 2, i = (t >> 1) & 1, j = t & 1;
    int p = g_topk[(z << 8) + ki];
    int pi = p >> 5, pj = p & 31;
    int b = z >> 2, h = z & 3;
    g_y0[((long long)b*Cn + (h*HDn + d))*4096 + (2*pi + i)*64 + (2*pj + j)] += g_outfT[idx];
}

// depthwise 3x3 + BN1 + relu6 -> t1 bf16 planes
__global__ void k_dw(const float* __restrict__ dw_w) {
    int idx = blockIdx.x * 256 + threadIdx.x;      // 2^21
    int x4 = (idx & 15) << 2, y = (idx >> 4) & 63, c = (idx >> 10) & 255, b = idx >> 18;
    const float* base = g_y0 + ((long long)b*Cn + c)*4096;
    const float* wp = dw_w + c*9;
    float s[4] = {0.f, 0.f, 0.f, 0.f};
    #pragma unroll
    for (int ky = 0; ky < 3; ky++) {
        int yy = y + ky - 1;
        if (yy < 0 || yy >= 64) continue;
        const float* row = base + yy*64;
        float4 mid = *(const float4*)(row + x4);
        float lft = (x4 > 0)  ? row[x4 - 1] : 0.f;
        float rgt = (x4 < 60) ? row[x4 + 4] : 0.f;
        float w0 = wp[ky*3], w1 = wp[ky*3 + 1], w2 = wp[ky*3 + 2];
        s[0] = fmaf(lft,   w0, fmaf(mid.x, w1, fmaf(mid.y, w2, s[0])));
        s[1] = fmaf(mid.x, w0, fmaf(mid.y, w1, fmaf(mid.z, w2, s[1])));
        s[2] = fmaf(mid.y, w0, fmaf(mid.z, w1, fmaf(mid.w, w2, s[2])));
        s[3] = fmaf(mid.z, w0, fmaf(mid.w, w1, fmaf(rgt,   w2, s[3])));
    }
    float sc = g_bn1sc[c], sh = g_bn1sh[c];
    float4 r;
    r.x = fminf(fmaxf(s[0]*sc + sh, 0.f), 6.f);
    r.y = fminf(fmaxf(s[1]*sc + sh, 0.f), 6.f);
    r.z = fminf(fmaxf(s[2]*sc + sh, 0.f), 6.f);
    r.w = fminf(fmaxf(s[3]*sc + sh, 0.f), 6.f);
    uint2 hv, lv; split4(r, hv, lv);
    size_t o = ((size_t)b*Cn + c)*4096 + y*64 + x4;
    *(uint2*)&g_t1h[o] = hv;
    *(uint2*)&g_t1l[o] = lv;
}

// ---------------- host ----------------
struct GArgs {
    const bf *Ah, *Al, *Bh, *Bl;
    float* Cf; bf *Ch, *Cl;
};
// mode 0: A=MxK, B=KxN ; mode 1: A=KxM, B=KxN ; mode 2: A=MxK, B=NxK
static void tg(int mode, GArgs g,
               int M, int N, int K, int lda, int ldb, int ldc,
               long long sA, long long sB, long long sC, int Z,
               float alpha, const float* sc, const float* sh, float lo, float hi)
{
    dim3 grid(N / 128, (M + 127) / 128, Z), blk(256);
    size_t shm = SMEM_HG;
    if (mode == 0) {
        cudaFuncSetAttribute(hgemm<false,true>, cudaFuncAttributeMaxDynamicSharedMemorySize, (int)shm);
        hgemm<false,true><<<grid, blk, shm>>>(g.Ah, g.Al, g.Bh, g.Bl, g.Cf, g.Ch, g.Cl,
                                              M, N, K, lda, ldb, ldc, sA, sB, sC, alpha, sc, sh, lo, hi);
    } else if (mode == 1) {
        cudaFuncSetAttribute(hgemm<true,true>, cudaFuncAttributeMaxDynamicSharedMemorySize, (int)shm);
        hgemm<true,true><<<grid, blk, shm>>>(g.Ah, g.Al, g.Bh, g.Bl, g.Cf, g.Ch, g.Cl,
                                             M, N, K, lda, ldb, ldc, sA, sB, sC, alpha, sc, sh, lo, hi);
    } else {
        cudaFuncSetAttribute(hgemm<false,false>, cudaFuncAttributeMaxDynamicSharedMemorySize, (int)shm);
        hgemm<false,false><<<grid, blk, shm>>>(g.Ah, g.Al, g.Bh, g.Bl, g.Cf, g.Ch, g.Cl,
                                               M, N, K, lda, ldb, ldc, sA, sB, sC, alpha, sc, sh, lo, hi);
    }
}

extern "C" void kernel_launch(void* const* d_in, const int* in_sizes, int n_in,
                              void* d_out, int out_size)
{
    const float* x      = (const float*)d_in[0];
    const float* down_w = (const float*)d_in[1];
    const float* down_b = (const float*)d_in[2];
    const float* up_w   = (const float*)d_in[3];
    const float* up_b   = (const float*)d_in[4];
    const float* wqkv_c = (const float*)d_in[5];
    const float* bqkv_c = (const float*)d_in[6];
    const float* wqkv_f = (const float*)d_in[7];
    const float* bqkv_f = (const float*)d_in[8];
    const float* dw_w   = (const float*)d_in[9];
    const float* bn1_g  = (const float*)d_in[10];
    const float* bn1_b  = (const float*)d_in[11];
    const float* bn1_m  = (const float*)d_in[12];
    const float* bn1_v  = (const float*)d_in[13];
    const float* pw_w   = (const float*)d_in[14];
    const float* bn2_g  = (const float*)d_in[15];
    const float* bn2_b  = (const float*)d_in[16];
    const float* bn2_m  = (const float*)d_in[17];
    const float* bn2_v  = (const float*)d_in[18];
    float* out = (float*)d_out;

    #define SYM(p, s) cudaGetSymbolAddress((void**)&p, s)
    bf *colh, *coll, *xdh, *xdl, *qch, *qcl, *qfh, *qfl, *Ph, *Pl, *tokh, *tokl;
    bf *t1h, *t1l, *wdh, *wdl, *Wph, *Wpl, *wqch, *wqcl, *wqfh, *wqfl, *pwh, *pwl;
    float *S, *outc, *c4, *coarse, *y0, *outf;
    float *b1s, *b1h, *b2s, *b2h;
    SYM(colh, g_colh); SYM(coll, g_coll); SYM(xdh, g_xdh); SYM(xdl, g_xdl);
    SYM(qch, g_qch); SYM(qcl, g_qcl); SYM(qfh, g_qfh); SYM(qfl, g_qfl);
    SYM(Ph, g_Ph); SYM(Pl, g_Pl); SYM(tokh, g_tokh); SYM(tokl, g_tokl);
    SYM(t1h, g_t1h); SYM(t1l, g_t1l); SYM(wdh, g_wdh); SYM(wdl, g_wdl);
    SYM(Wph, g_Wph); SYM(Wpl, g_Wpl); SYM(wqch, g_wqch); SYM(wqcl, g_wqcl);
    SYM(wqfh, g_wqfh); SYM(wqfl, g_wqfl); SYM(pwh, g_pwh); SYM(pwl, g_pwl);
    SYM(S, g_S); SYM(outc, g_outc); SYM(c4, g_coarse4); SYM(coarse, g_coarse);
    SYM(y0, g_y0); SYM(outf, g_outfT);
    SYM(b1s, g_bn1sc); SYM(b1h, g_bn1sh); SYM(b2s, g_bn2sc); SYM(b2h, g_bn2sh);
    #undef SYM

    const float NEG = -3.0e38f, POS = 3.0e38f;

    // weight prep + constants
    k_bnprep<<<1, 256>>>(bn1_g, bn1_b, bn1_m, bn1_v, b1s, b1h);
    k_bnprep<<<1, 256>>>(bn2_g, bn2_b, bn2_m, bn2_v, b2s, b2h);
    k_prep<<<4096, 256>>>(down_w, wdh, wdl, 256, 4096, 0);
    k_prep<<<48, 256>>>(wqkv_c, wqch, wqcl, 192, 64, 1);
    k_prep<<<48, 256>>>(wqkv_f, wqfh, wqfl, 192, 64, 1);
    k_prep<<<256, 256>>>(pw_w, pwh, pwl, 256, 256, 0);
    k_wp<<<4096, 256>>>(up_w);

    // ---- down conv -> xd planes
    k_im2col_down<<<32768, 256>>>(x);
    tg(0, {wdh, wdl, colh, coll, nullptr, xdh, xdl}, 256, 1024, 4096, 4096, 1024, 1024,
       0, 4096LL*1024, 256LL*1024, Bn, 1.f, nullptr, down_b, NEG, POS);

    // ---- coarse QKV -> qkvT planes
    tg(0, {wqch, wqcl, xdh, xdl, nullptr, qch, qcl}, 192, 1024, 64, 64, 1024, 1024,
       0, 65536, 192LL*1024, 32, 1.f, nullptr, bqkv_c, NEG, POS);

    // ---- coarse S = q^T k * scale -> fp32, softmax -> P planes
    tg(1, {qch, qcl, qch + 65536, qcl + 65536, S, nullptr, nullptr}, 1024, 1024, 64, 1024, 1024, 1024,
       196608, 196608, 1048576, 32, 0.125f, nullptr, nullptr, NEG, POS);
    k_softmax<<<32768, 256>>>(S, Ph, Pl);
    k_colsum<<<128, 256>>>();
    k_topk<<<32, 512>>>();

    // ---- coarse out: outc = vT @ P^T (fp32)
    tg(2, {qch + 131072, qcl + 131072, Ph, Pl, outc, nullptr, nullptr}, 64, 1024, 1024, 1024, 1024, 1024,
       196608, 1048576, 65536, 32, 1.f, nullptr, nullptr, NEG, POS);

    // ---- up conv transpose: 4 parity GEMMs, interleave(+copy to y0)
    k_im2col_up<<<32768, 256>>>();
    for (int par = 0; par < 4; par++) {
        tg(0, {Wph + (long long)par*262144, Wpl + (long long)par*262144,
               colh + (long long)par*1048576, coll + (long long)par*1048576,
               c4 + (long long)par*262144, nullptr, nullptr}, 256, 1024, 1024, 1024, 1024, 1024,
           0, 4194304, 1048576, Bn, 1.f, nullptr, up_b, NEG, POS);
    }
    k_interleave<<<32768, 256>>>();

    // ---- fine attention
    k_gather_fine<<<8192, 256>>>();
    tg(0, {wqfh, wqfl, tokh, tokl, nullptr, qfh, qfl}, 192, 1024, 64, 64, 1024, 1024,
       0, 65536, 192LL*1024, 32, 1.f, nullptr, bqkv_f, NEG, POS);
    tg(1, {qfh, qfl, qfh + 65536, qfl + 65536, S, nullptr, nullptr}, 1024, 1024, 64, 1024, 1024, 1024,
       196608, 196608, 1048576, 32, 0.125f, nullptr, nullptr, NEG, POS);
    k_softmax<<<32768, 256>>>(S, Ph, Pl);
    tg(2, {qfh + 131072, qfl + 131072, Ph, Pl, outf, nullptr, nullptr}, 64, 1024, 1024, 1024, 1024, 1024,
       196608, 1048576, 65536, 32, 1.f, nullptr, nullptr, NEG, POS);

    // ---- residual add of fine output into y0
    k_scatter<<<8192, 256>>>();

    // ---- depthwise 3x3 + BN1 + relu6 -> t1 planes
    k_dw<<<8192, 256>>>(dw_w);

    // ---- pointwise 1x1 + BN2 + relu6 -> out
    tg(0, {pwh, pwl, t1h, t1l, out, nullptr, nullptr}, 256, 4096, 256, 256, 4096, 4096,
       0, 1048576, 1048576, Bn, 1.f, b2s, b2h, 0.f, 6.f);
}

// round 6
// speedup vs baseline: 2.3499x; 1.0953x over previous
#include <cuda_runtime.h>
#include <cuda_bf16.h>
#include <math.h>
#include <stdint.h>

#define Bn 8
#define Cn 256
#define Hn 64
#define Wn 64
#define NHn 4
#define HDn 64
#define NTOK 1024
#define KFn 256

typedef __nv_bfloat16 bf;

// ---------------- static scratch ----------------
__device__ bf    g_colh[33554432], g_coll[33554432];
__device__ bf    g_xdh[2097152],  g_xdl[2097152];
__device__ bf    g_qch[6291456],  g_qcl[6291456];
__device__ bf    g_qfh[6291456],  g_qfl[6291456];
__device__ float g_S[33554432];
__device__ bf    g_Ph[33554432],  g_Pl[33554432];
__device__ float g_score[Bn*NHn*NTOK];
__device__ int   g_topk[Bn*NHn*KFn];
__device__ float g_outc[Bn*Cn*1024];
__device__ bf    g_tokh[2097152], g_tokl[2097152];
__device__ float g_outfT[2097152];
__device__ float g_coarse4[33554432];
__device__ float g_coarse[8388608];
__device__ float g_y0[8388608];
__device__ bf    g_t1h[8388608],  g_t1l[8388608];
__device__ bf    g_wdh[1048576],  g_wdl[1048576];
__device__ bf    g_Wph[1048576],  g_Wpl[1048576];
__device__ bf    g_wqch[12288],   g_wqcl[12288];
__device__ bf    g_wqfh[12288],   g_wqfl[12288];
__device__ bf    g_pwh[65536],    g_pwl[65536];
__device__ float g_bn1sc[Cn], g_bn1sh[Cn], g_bn2sc[Cn], g_bn2sh[Cn];

// ================= helpers =================
__device__ __forceinline__ void ldsm4(uint32_t* r, uint32_t addr) {
    asm volatile("ldmatrix.sync.aligned.m8n8.x4.shared.b16 {%0,%1,%2,%3}, [%4];"
                 : "=r"(r[0]), "=r"(r[1]), "=r"(r[2]), "=r"(r[3]) : "r"(addr));
}
__device__ __forceinline__ void ldsm4t(uint32_t* r, uint32_t addr) {
    asm volatile("ldmatrix.sync.aligned.m8n8.x4.trans.shared.b16 {%0,%1,%2,%3}, [%4];"
                 : "=r"(r[0]), "=r"(r[1]), "=r"(r[2]), "=r"(r[3]) : "r"(addr));
}
__device__ __forceinline__ void mma16816(float* d, const uint32_t* a, const uint32_t* b) {
    asm volatile("mma.sync.aligned.m16n8k16.row.col.f32.bf16.bf16.f32 "
                 "{%0,%1,%2,%3},{%4,%5,%6,%7},{%8,%9},{%0,%1,%2,%3};"
                 : "+f"(d[0]), "+f"(d[1]), "+f"(d[2]), "+f"(d[3])
                 : "r"(a[0]), "r"(a[1]), "r"(a[2]), "r"(a[3]), "r"(b[0]), "r"(b[1]));
}
__device__ __forceinline__ void cpa16(uint32_t dst, const void* src) {
    asm volatile("cp.async.cg.shared.global [%0], [%1], 16;" :: "r"(dst), "l"(src));
}
#define CP_COMMIT() asm volatile("cp.async.commit_group;" ::: "memory")
#define CP_WAIT0()  asm volatile("cp.async.wait_group 0;" ::: "memory")

__device__ __forceinline__ uint32_t packbf2(float a, float b) {
    __nv_bfloat162 t;
    t.x = __float2bfloat16_rn(a); t.y = __float2bfloat16_rn(b);
    return *(uint32_t*)&t;
}
__device__ __forceinline__ void split4(float4 f, uint2& hv, uint2& lv) {
    float hx = __bfloat162float(__float2bfloat16_rn(f.x));
    float hy = __bfloat162float(__float2bfloat16_rn(f.y));
    float hz = __bfloat162float(__float2bfloat16_rn(f.z));
    float hw = __bfloat162float(__float2bfloat16_rn(f.w));
    hv.x = packbf2(f.x, f.y);           hv.y = packbf2(f.z, f.w);
    lv.x = packbf2(f.x - hx, f.y - hy); lv.y = packbf2(f.z - hz, f.w - hw);
}
__device__ __forceinline__ void split1(float a, bf* oh, bf* ol) {
    bf h = __float2bfloat16_rn(a);
    *oh = h;
    *ol = __float2bfloat16_rn(a - __bfloat162float(h));
}

// ================= HMMA GEMM: 128x128 or 64x128 tiles =================
#define SLOT 10240
#define STAGE (4*SLOT)
#define SMEM_HG (2*STAGE)

template<bool ATR, bool BKN, bool M64T>
__global__ __launch_bounds__(256) void hgemm(
    const bf* __restrict__ Agh, const bf* __restrict__ Agl,
    const bf* __restrict__ Bgh, const bf* __restrict__ Bgl,
    float* __restrict__ Cf, bf* __restrict__ Ch, bf* __restrict__ Cl,
    int M, int N, int K, int lda, int ldb, int ldc,
    long long sA, long long sB, long long sC, int zamask,
    float alpha, const float* __restrict__ rowScale, const float* __restrict__ rowShift,
    float lo, float hi)
{
    constexpr int MT  = M64T ? 64 : 128;
    constexpr int NFP = M64T ? 2 : 4;
    constexpr int NWS = M64T ? 32 : 64;
    extern __shared__ char sm[];
    const uint32_t smb = (uint32_t)__cvta_generic_to_shared(sm);
    const int tid = threadIdx.x;
    const int wid = tid >> 5, lane = tid & 31;
    const int grp = lane >> 2, tig = lane & 3;
    const int z = blockIdx.z;
    const int za = z & zamask;
    Agh += (size_t)za * sA; Agl += (size_t)za * sA;
    Bgh += (size_t)z * sB;  Bgl += (size_t)z * sB;
    if (Cf) Cf += (size_t)z * sC;
    if (Ch) { Ch += (size_t)z * sC; Cl += (size_t)z * sC; }
    const int m0 = blockIdx.y * MT, n0 = blockIdx.x * 128;
    const int mw = M64T ? (wid >> 2) : (wid >> 1);
    const int nw = M64T ? (wid & 3) : (wid & 1);

    float acc[2][2*NFP][4];
    #pragma unroll
    for (int i = 0; i < 2; i++)
        #pragma unroll
        for (int j = 0; j < 2*NFP; j++)
            #pragma unroll
            for (int q = 0; q < 4; q++) acc[i][j][q] = 0.f;

    const int nch = K >> 5;

    auto stage_copy = [&](int c, int s) {
        const int k0 = c << 5;
        const uint32_t Ab = smb + s * STAGE;
        const uint32_t Bb = Ab + 2 * SLOT;
        #pragma unroll
        for (int p = 0; p < (M64T ? 1 : 2); p++) {
            int id = tid + (p << 8);
            if (!ATR) {
                int m = id >> 2, part = id & 3;
                size_t off = (size_t)(m0 + m) * lda + k0 + part * 8;
                uint32_t d = Ab + m * 80 + part * 16;
                cpa16(d, Agh + off);
                cpa16(d + SLOT, Agl + off);
            } else {
                int k = id >> 4, part = id & 15;
                size_t off = (size_t)(k0 + k) * lda + m0 + part * 8;
                uint32_t d = Ab + k * 272 + part * 16;
                cpa16(d, Agh + off);
                cpa16(d + SLOT, Agl + off);
            }
        }
        #pragma unroll
        for (int p = 0; p < 2; p++) {
            int id = tid + (p << 8);
            if (BKN) {
                int k = id >> 4, part = id & 15;
                size_t off = (size_t)(k0 + k) * ldb + n0 + part * 8;
                uint32_t d = Bb + k * 272 + part * 16;
                cpa16(d, Bgh + off);
                cpa16(d + SLOT, Bgl + off);
            } else {
                int n = id >> 2, part = id & 3;
                size_t off = (size_t)(n0 + n) * ldb + k0 + part * 8;
                uint32_t d = Bb + n * 80 + part * 16;
                cpa16(d, Bgh + off);
                cpa16(d + SLOT, Bgl + off);
            }
        }
    };

    auto compute = [&](int s) {
        const uint32_t Ab = smb + s * STAGE;
        const uint32_t Bb = Ab + 2 * SLOT;
        const int i = lane >> 3;
        #pragma unroll
        for (int kk = 0; kk < 32; kk += 16) {
            uint32_t ah[2][4], al[2][4];
            #pragma unroll
            for (int mf = 0; mf < 2; mf++) {
                uint32_t addr;
                if (!ATR) {
                    addr = Ab + (uint32_t)((mw * 32 + mf * 16 + (lane & 15)) * 80 + (kk + (lane >> 4) * 8) * 2);
                    ldsm4(ah[mf], addr); ldsm4(al[mf], addr + SLOT);
                } else {
                    addr = Ab + (uint32_t)((kk + (i >> 1) * 8 + (lane & 7)) * 272 + (mw * 32 + mf * 16 + (i & 1) * 8) * 2);
                    ldsm4t(ah[mf], addr); ldsm4t(al[mf], addr + SLOT);
                }
            }
            uint32_t bh[NFP][4], bl[NFP][4];
            #pragma unroll
            for (int nfp = 0; nfp < NFP; nfp++) {
                uint32_t addr;
                if (BKN) {
                    addr = Bb + (uint32_t)((kk + (i & 1) * 8 + (lane & 7)) * 272 + (nw * NWS + nfp * 16 + (i >> 1) * 8) * 2);
                    ldsm4t(bh[nfp], addr); ldsm4t(bl[nfp], addr + SLOT);
                } else {
                    addr = Bb + (uint32_t)((nw * NWS + nfp * 16 + (i >> 1) * 8 + (lane & 7)) * 80 + (kk + (i & 1) * 8) * 2);
                    ldsm4(bh[nfp], addr); ldsm4(bl[nfp], addr + SLOT);
                }
            }
            #pragma unroll
            for (int pass = 0; pass < 3; pass++) {
                #pragma unroll
                for (int nfp = 0; nfp < NFP; nfp++) {
                    #pragma unroll
                    for (int mf = 0; mf < 2; mf++) {
                        #pragma unroll
                        for (int h = 0; h < 2; h++) {
                            const uint32_t* a = (pass == 2) ? al[mf] : ah[mf];
                            const uint32_t* b = ((pass == 1) ? bl[nfp] : bh[nfp]) + h * 2;
                            mma16816(acc[mf][nfp * 2 + h], a, b);
                        }
                    }
                }
            }
        }
    };

    stage_copy(0, 0); CP_COMMIT();
    for (int c = 0; c < nch; c++) {
        CP_WAIT0();
        __syncthreads();
        if (c + 1 < nch) { stage_copy(c + 1, (c + 1) & 1); CP_COMMIT(); }
        compute(c & 1);
    }
    __syncthreads();

    // ---- epilogue ----
    float* stg = (float*)sm;   // [MT][132]
    #pragma unroll
    for (int mf = 0; mf < 2; mf++) {
        int r0 = mw * 32 + mf * 16 + grp;
        float av0 = alpha, av1 = alpha, sh0 = 0.f, sh1 = 0.f;
        if (rowScale) { av0 *= rowScale[m0 + r0]; av1 *= rowScale[m0 + r0 + 8]; }
        if (rowShift) { sh0 = rowShift[m0 + r0]; sh1 = rowShift[m0 + r0 + 8]; }
        #pragma unroll
        for (int nf = 0; nf < 2*NFP; nf++) {
            int cb = nw * NWS + nf * 8 + tig * 2;
            float* d = acc[mf][nf];
            stg[r0 * 132 + cb]           = fminf(fmaxf(d[0] * av0 + sh0, lo), hi);
            stg[r0 * 132 + cb + 1]       = fminf(fmaxf(d[1] * av0 + sh0, lo), hi);
            stg[(r0 + 8) * 132 + cb]     = fminf(fmaxf(d[2] * av1 + sh1, lo), hi);
            stg[(r0 + 8) * 132 + cb + 1] = fminf(fmaxf(d[3] * av1 + sh1, lo), hi);
        }
    }
    __syncthreads();
    if (Cf) {
        #pragma unroll
        for (int it = 0; it < MT/8; it++) {
            int lin = tid + (it << 8);
            int rr = lin >> 5, c4 = (lin & 31) << 2;
            *(float4*)(Cf + (size_t)(m0 + rr) * ldc + n0 + c4) = *(float4*)&stg[rr * 132 + c4];
        }
    } else {
        #pragma unroll
        for (int it = 0; it < MT/8; it++) {
            int lin = tid + (it << 8);
            int rr = lin >> 5, c4 = (lin & 31) << 2;
            float4 v = *(float4*)&stg[rr * 132 + c4];
            uint2 hv, lv;
            split4(v, hv, lv);
            size_t o = (size_t)(m0 + rr) * ldc + n0 + c4;
            *(uint2*)(Ch + o) = hv;
            *(uint2*)(Cl + o) = lv;
        }
    }
}

// ---------------- fused weight prep ----------------
#define PREP_O2 1048576
#define PREP_O3 1060864
#define PREP_O4 1073152
#define PREP_O5 1138688
#define PREP_O6 2187264
#define PREP_END 2187776
__global__ void k_prep_all(const float* __restrict__ down_w,
                           const float* __restrict__ wqkv_c, const float* __restrict__ wqkv_f,
                           const float* __restrict__ pw_w,   const float* __restrict__ up_w,
                           const float* __restrict__ bn1_g, const float* __restrict__ bn1_b,
                           const float* __restrict__ bn1_m, const float* __restrict__ bn1_v,
                           const float* __restrict__ bn2_g, const float* __restrict__ bn2_b,
                           const float* __restrict__ bn2_m, const float* __restrict__ bn2_v) {
    int idx = blockIdx.x * 256 + threadIdx.x;
    if (idx < PREP_O2) {
        split1(down_w[idx], g_wdh + idx, g_wdl + idx);
    } else if (idx < PREP_O3) {
        int i = idx - PREP_O2;
        int m = i / 64, k = i % 64;
        split1(wqkv_c[k * 192 + m], g_wqch + i, g_wqcl + i);
    } else if (idx < PREP_O4) {
        int i = idx - PREP_O3;
        int m = i / 64, k = i % 64;
        split1(wqkv_f[k * 192 + m], g_wqfh + i, g_wqfl + i);
    } else if (idx < PREP_O5) {
        int i = idx - PREP_O4;
        split1(pw_w[i], g_pwh + i, g_pwl + i);
    } else if (idx < PREP_O6) {
        int i = idx - PREP_O5;
        int k = i & 1023, co = (i >> 10) & 255, p = i >> 18;
        int tj = k & 1, ti = (k >> 1) & 1, ci = k >> 2;
        int px = p & 1, py = p >> 1;
        int kh = (py == 0) ? (ti == 0 ? 1 : 3) : (ti == 0 ? 0 : 2);
        int kw = (px == 0) ? (tj == 0 ? 1 : 3) : (tj == 0 ? 0 : 2);
        split1(up_w[((ci << 8) + co) * 16 + kh*4 + kw], g_Wph + i, g_Wpl + i);
    } else if (idx < PREP_END) {
        int i = idx - PREP_O6;
        int c = i & 255;
        if (i < 256) {
            float inv = bn1_g[c] / sqrtf(bn1_v[c] + 1e-5f);
            g_bn1sc[c] = inv;
            g_bn1sh[c] = bn1_b[c] - bn1_m[c] * inv;
        } else {
            float inv = bn2_g[c] / sqrtf(bn2_v[c] + 1e-5f);
            g_bn2sc[c] = inv;
            g_bn2sh[c] = bn2_b[c] - bn2_m[c] * inv;
        }
    }
}

// ---------------- elementwise kernels ----------------
__global__ void k_im2col_down(const float* __restrict__ x) {
    int idx = blockIdx.x * 256 + threadIdx.x;
    int q  = idx & 255;
    int k  = (idx >> 8) & 4095;
    int b  = idx >> 20;
    int kw = k & 3, kh = (k >> 2) & 3, ci = k >> 4;
    int ow0 = (q & 7) << 2, oh = q >> 3;
    int ih = oh*2 - 1 + kh;
    const float* xr = x + ((long long)b*Cn + ci)*(Hn*Wn) + ih*Wn;
    float4 r;
    float* rp = (float*)&r;
    #pragma unroll
    for (int j = 0; j < 4; j++) {
        int iw = (ow0 + j)*2 - 1 + kw;
        rp[j] = (ih >= 0 && ih < Hn && iw >= 0 && iw < Wn) ? xr[iw] : 0.f;
    }
    uint2 hv, lv; split4(r, hv, lv);
    size_t o = ((size_t)idx) << 2;
    *(uint2*)&g_colh[o] = hv;
    *(uint2*)&g_coll[o] = lv;
}

__global__ void k_im2col_up() {
    int idx = blockIdx.x * 256 + threadIdx.x;
    int q = idx & 255;
    int k = (idx >> 8) & 1023;
    int s = idx >> 18;
    int tj = k & 1, ti = (k >> 1) & 1, ci = k >> 2;
    int px = s & 1, py = (s >> 1) & 1, b = s >> 2;
    int c0 = (q & 7) << 2, a = q >> 3;
    int iy = (py == 0) ? (ti == 0 ? a : a - 1) : (ti == 0 ? a + 1 : a);
    int dx = (px == 0) ? (tj == 0 ? 0 : -1) : (tj == 0 ? 1 : 0);
    const float* orow = g_outc + ((long long)b*Cn + ci)*1024 + iy*32;
    float4 r;
    float* rp = (float*)&r;
    bool rowok = (iy >= 0 && iy < 32);
    #pragma unroll
    for (int j = 0; j < 4; j++) {
        int ix = c0 + j + dx;
        rp[j] = (rowok && ix >= 0 && ix < 32) ? orow[ix] : 0.f;
    }
    uint2 hv, lv; split4(r, hv, lv);
    size_t o = ((size_t)idx) << 2;
    *(uint2*)&g_colh[o] = hv;
    *(uint2*)&g_coll[o] = lv;
}

__global__ void k_interleave() {
    int idx = blockIdx.x * 256 + threadIdx.x;
    int n = idx & 1023, co = (idx >> 10) & 255, s = idx >> 18;
    int px = s & 1, py = (s >> 1) & 1, b = s >> 2;
    int c = n & 31, a = n >> 5;
    float v = g_coarse4[idx];
    long long o = ((long long)b*Cn + co)*4096 + (2*a + py)*64 + (2*c + px);
    g_coarse[o] = v;
    g_y0[o] = v;
}

__global__ __launch_bounds__(256) void k_softmax(const float* __restrict__ S,
                                                 bf* __restrict__ Ph, bf* __restrict__ Pl) {
    __shared__ float red[8];
    long long row = blockIdx.x;
    const float* p = S + row * 1024;
    int tid = threadIdx.x;
    float4 v = ((const float4*)p)[tid];
    float mx = fmaxf(fmaxf(v.x, v.y), fmaxf(v.z, v.w));
    #pragma unroll
    for (int o = 16; o; o >>= 1) mx = fmaxf(mx, __shfl_xor_sync(0xffffffffu, mx, o));
    if ((tid & 31) == 0) red[tid >> 5] = mx;
    __syncthreads();
    if (tid == 0) {
        float m = red[0];
        #pragma unroll
        for (int i = 1; i < 8; i++) m = fmaxf(m, red[i]);
        red[0] = m;
    }
    __syncthreads();
    mx = red[0];
    __syncthreads();
    float e0 = __expf(v.x - mx), e1 = __expf(v.y - mx);
    float e2 = __expf(v.z - mx), e3 = __expf(v.w - mx);
    float s = (e0 + e1) + (e2 + e3);
    #pragma unroll
    for (int o = 16; o; o >>= 1) s += __shfl_xor_sync(0xffffffffu, s, o);
    if ((tid & 31) == 0) red[tid >> 5] = s;
    __syncthreads();
    if (tid == 0) {
        float t = 0.f;
        #pragma unroll
        for (int i = 0; i < 8; i++) t += red[i];
        red[0] = t;
    }
    __syncthreads();
    float inv = 1.f / red[0];
    float4 r;
    r.x = e0 * inv; r.y = e1 * inv; r.z = e2 * inv; r.w = e3 * inv;
    uint2 hv, lv; split4(r, hv, lv);
    size_t o = row * 1024 + (size_t)tid * 4;
    *(uint2*)(Ph + o) = hv;
    *(uint2*)(Pl + o) = lv;
}

__global__ void k_colsum() {
    int z = blockIdx.x >> 2;
    int m = ((blockIdx.x & 3) << 8) + threadIdx.x;
    const bf* ph = g_Ph + (long long)z * 1048576 + m;
    const bf* pl = g_Pl + (long long)z * 1048576 + m;
    float s = 0.f;
    #pragma unroll 8
    for (int n = 0; n < 1024; n++) {
        long long o = (long long)n << 10;
        s += __bfloat162float(ph[o]) + __bfloat162float(pl[o]);
    }
    g_score[z * 1024 + m] = s;
}

__global__ __launch_bounds__(512) void k_topk() {
    __shared__ float v[1024];
    __shared__ int   ix[1024];
    int z = blockIdx.x, tid = threadIdx.x;
    for (int i = tid; i < 1024; i += 512) { v[i] = g_score[z*1024 + i]; ix[i] = i; }
    __syncthreads();
    for (int k = 2; k <= 1024; k <<= 1) {
        for (int j = k >> 1; j > 0; j >>= 1) {
            for (int i = tid; i < 1024; i += 512) {
                int l = i ^ j;
                if (l > i) {
                    bool up = ((i & k) == 0);
                    bool sw = up ? (v[i] < v[l]) : (v[i] > v[l]);
                    if (sw) {
                        float tv = v[i]; v[i] = v[l]; v[l] = tv;
                        int ti2 = ix[i]; ix[i] = ix[l]; ix[l] = ti2;
                    }
                }
            }
            __syncthreads();
        }
    }
    for (int i = tid; i < KFn; i += 512) g_topk[z*KFn + i] = ix[i];
}

__global__ void k_gather_fine() {
    int idx = blockIdx.x * 256 + threadIdx.x;
    int t = idx & 1023, d = (idx >> 10) & 63, z = idx >> 16;
    int ki = t >> 2, i = (t >> 1) & 1, j = t & 1;
    int p = g_topk[(z << 8) + ki];
    int pi = p >> 5, pj = p & 31;
    int b = z >> 2, h = z & 3;
    float v = g_coarse[((long long)b*Cn + (h*HDn + d))*4096 + (2*pi + i)*64 + (2*pj + j)];
    split1(v, g_tokh + idx, g_tokl + idx);
}

__global__ void k_scatter() {
    int idx = blockIdx.x * 256 + threadIdx.x;
    int t = idx & 1023, d = (idx >> 10) & 63, z = idx >> 16;
    int ki = t >> 2, i = (t >> 1) & 1, j = t & 1;
    int p = g_topk[(z << 8) + ki];
    int pi = p >> 5, pj = p & 31;
    int b = z >> 2, h = z & 3;
    g_y0[((long long)b*Cn + (h*HDn + d))*4096 + (2*pi + i)*64 + (2*pj + j)] += g_outfT[idx];
}

__global__ void k_dw(const float* __restrict__ dw_w) {
    int idx = blockIdx.x * 256 + threadIdx.x;
    int x4 = (idx & 15) << 2, y = (idx >> 4) & 63, c = (idx >> 10) & 255, b = idx >> 18;
    const float* base = g_y0 + ((long long)b*Cn + c)*4096;
    const float* wp = dw_w + c*9;
    float s[4] = {0.f, 0.f, 0.f, 0.f};
    #pragma unroll
    for (int ky = 0; ky < 3; ky++) {
        int yy = y + ky - 1;
        if (yy < 0 || yy >= 64) continue;
        const float* row = base + yy*64;
        float4 mid = *(const float4*)(row + x4);
        float lft = (x4 > 0)  ? row[x4 - 1] : 0.f;
        float rgt = (x4 < 60) ? row[x4 + 4] : 0.f;
        float w0 = wp[ky*3], w1 = wp[ky*3 + 1], w2 = wp[ky*3 + 2];
        s[0] = fmaf(lft,   w0, fmaf(mid.x, w1, fmaf(mid.y, w2, s[0])));
        s[1] = fmaf(mid.x, w0, fmaf(mid.y, w1, fmaf(mid.z, w2, s[1])));
        s[2] = fmaf(mid.y, w0, fmaf(mid.z, w1, fmaf(mid.w, w2, s[2])));
        s[3] = fmaf(mid.z, w0, fmaf(mid.w, w1, fmaf(rgt,   w2, s[3])));
    }
    float sc = g_bn1sc[c], sh = g_bn1sh[c];
    float4 r;
    r.x = fminf(fmaxf(s[0]*sc + sh, 0.f), 6.f);
    r.y = fminf(fmaxf(s[1]*sc + sh, 0.f), 6.f);
    r.z = fminf(fmaxf(s[2]*sc + sh, 0.f), 6.f);
    r.w = fminf(fmaxf(s[3]*sc + sh, 0.f), 6.f);
    uint2 hv, lv; split4(r, hv, lv);
    size_t o = ((size_t)b*Cn + c)*4096 + y*64 + x4;
    *(uint2*)&g_t1h[o] = hv;
    *(uint2*)&g_t1l[o] = lv;
}

// ---------------- host ----------------
struct GArgs {
    const bf *Ah, *Al, *Bh, *Bl;
    float* Cf; bf *Ch, *Cl;
};
// mode 0: A=MxK,B=KxN ; mode 1: A=KxM,B=KxN ; mode 2: A=MxK,B=NxK
// m64: use 64-row tiles
static void tg(int mode, bool m64, GArgs g,
               int M, int N, int K, int lda, int ldb, int ldc,
               long long sA, long long sB, long long sC, int Z, int zamask,
               float alpha, const float* sc, const float* sh, float lo, float hi)
{
    dim3 grid(N / 128, M / (m64 ? 64 : 128), Z), blk(256);
    size_t shm = SMEM_HG;
    if (mode == 0 && !m64) {
        cudaFuncSetAttribute(hgemm<false,true,false>, cudaFuncAttributeMaxDynamicSharedMemorySize, (int)shm);
        hgemm<false,true,false><<<grid, blk, shm>>>(g.Ah, g.Al, g.Bh, g.Bl, g.Cf, g.Ch, g.Cl,
            M, N, K, lda, ldb, ldc, sA, sB, sC, zamask, alpha, sc, sh, lo, hi);
    } else if (mode == 0 && m64) {
        cudaFuncSetAttribute(hgemm<false,true,true>, cudaFuncAttributeMaxDynamicSharedMemorySize, (int)shm);
        hgemm<false,true,true><<<grid, blk, shm>>>(g.Ah, g.Al, g.Bh, g.Bl, g.Cf, g.Ch, g.Cl,
            M, N, K, lda, ldb, ldc, sA, sB, sC, zamask, alpha, sc, sh, lo, hi);
    } else if (mode == 1) {
        cudaFuncSetAttribute(hgemm<true,true,false>, cudaFuncAttributeMaxDynamicSharedMemorySize, (int)shm);
        hgemm<true,true,false><<<grid, blk, shm>>>(g.Ah, g.Al, g.Bh, g.Bl, g.Cf, g.Ch, g.Cl,
            M, N, K, lda, ldb, ldc, sA, sB, sC, zamask, alpha, sc, sh, lo, hi);
    } else {
        cudaFuncSetAttribute(hgemm<false,false,true>, cudaFuncAttributeMaxDynamicSharedMemorySize, (int)shm);
        hgemm<false,false,true><<<grid, blk, shm>>>(g.Ah, g.Al, g.Bh, g.Bl, g.Cf, g.Ch, g.Cl,
            M, N, K, lda, ldb, ldc, sA, sB, sC, zamask, alpha, sc, sh, lo, hi);
    }
}

extern "C" void kernel_launch(void* const* d_in, const int* in_sizes, int n_in,
                              void* d_out, int out_size)
{
    const float* x      = (const float*)d_in[0];
    const float* down_w = (const float*)d_in[1];
    const float* down_b = (const float*)d_in[2];
    const float* up_w   = (const float*)d_in[3];
    const float* up_b   = (const float*)d_in[4];
    const float* wqkv_c = (const float*)d_in[5];
    const float* bqkv_c = (const float*)d_in[6];
    const float* wqkv_f = (const float*)d_in[7];
    const float* bqkv_f = (const float*)d_in[8];
    const float* dw_w   = (const float*)d_in[9];
    const float* bn1_g  = (const float*)d_in[10];
    const float* bn1_b  = (const float*)d_in[11];
    const float* bn1_m  = (const float*)d_in[12];
    const float* bn1_v  = (const float*)d_in[13];
    const float* pw_w   = (const float*)d_in[14];
    const float* bn2_g  = (const float*)d_in[15];
    const float* bn2_b  = (const float*)d_in[16];
    const float* bn2_m  = (const float*)d_in[17];
    const float* bn2_v  = (const float*)d_in[18];
    float* out = (float*)d_out;

    #define SYM(p, s) cudaGetSymbolAddress((void**)&p, s)
    bf *colh, *coll, *xdh, *xdl, *qch, *qcl, *qfh, *qfl, *Ph, *Pl, *tokh, *tokl;
    bf *t1h, *t1l, *wdh, *wdl, *Wph, *Wpl, *wqch, *wqcl, *wqfh, *wqfl, *pwh, *pwl;
    float *S, *outc, *c4, *outf;
    float *b2s, *b2h;
    SYM(colh, g_colh); SYM(coll, g_coll); SYM(xdh, g_xdh); SYM(xdl, g_xdl);
    SYM(qch, g_qch); SYM(qcl, g_qcl); SYM(qfh, g_qfh); SYM(qfl, g_qfl);
    SYM(Ph, g_Ph); SYM(Pl, g_Pl); SYM(tokh, g_tokh); SYM(tokl, g_tokl);
    SYM(t1h, g_t1h); SYM(t1l, g_t1l); SYM(wdh, g_wdh); SYM(wdl, g_wdl);
    SYM(Wph, g_Wph); SYM(Wpl, g_Wpl); SYM(wqch, g_wqch); SYM(wqcl, g_wqcl);
    SYM(wqfh, g_wqfh); SYM(wqfl, g_wqfl); SYM(pwh, g_pwh); SYM(pwl, g_pwl);
    SYM(S, g_S); SYM(outc, g_outc); SYM(c4, g_coarse4);
    SYM(outf, g_outfT);
    SYM(b2s, g_bn2sc); SYM(b2h, g_bn2sh);
    #undef SYM

    const float NEG = -3.0e38f, POS = 3.0e38f;
    const int ZM = 0x7fffffff;

    // fused weight prep
    k_prep_all<<<(PREP_END + 255)/256, 256>>>(down_w, wqkv_c, wqkv_f, pw_w, up_w,
        bn1_g, bn1_b, bn1_m, bn1_v, bn2_g, bn2_b, bn2_m, bn2_v);

    // ---- down conv -> xd planes (M64: 256 CTAs)
    k_im2col_down<<<32768, 256>>>(x);
    tg(0, true, {wdh, wdl, colh, coll, nullptr, xdh, xdl}, 256, 1024, 4096, 4096, 1024, 1024,
       0, 4096LL*1024, 256LL*1024, Bn, ZM, 1.f, nullptr, down_b, NEG, POS);

    // ---- coarse QKV (M=192, M64: no waste)
    tg(0, true, {wqch, wqcl, xdh, xdl, nullptr, qch, qcl}, 192, 1024, 64, 64, 1024, 1024,
       0, 65536, 196608, 32, ZM, 1.f, nullptr, bqkv_c, NEG, POS);

    // ---- coarse S, softmax, colsum, topk
    tg(1, false, {qch, qcl, qch + 65536, qcl + 65536, S, nullptr, nullptr}, 1024, 1024, 64, 1024, 1024, 1024,
       196608, 196608, 1048576, 32, ZM, 0.125f, nullptr, nullptr, NEG, POS);
    k_softmax<<<32768, 256>>>(S, Ph, Pl);
    k_colsum<<<128, 256>>>();
    k_topk<<<32, 512>>>();

    // ---- coarse PV (M64: no waste)
    tg(2, true, {qch + 131072, qcl + 131072, Ph, Pl, outc, nullptr, nullptr}, 64, 1024, 1024, 1024, 1024, 1024,
       196608, 1048576, 65536, 32, ZM, 1.f, nullptr, nullptr, NEG, POS);

    // ---- up conv transpose: ONE fused launch over (b,par)
    k_im2col_up<<<32768, 256>>>();
    tg(0, false, {Wph, Wpl, colh, coll, c4, nullptr, nullptr}, 256, 1024, 1024, 1024, 1024, 1024,
       262144, 1048576, 262144, 32, 3, 1.f, nullptr, up_b, NEG, POS);
    k_interleave<<<32768, 256>>>();

    // ---- fine attention
    k_gather_fine<<<8192, 256>>>();
    tg(0, true, {wqfh, wqfl, tokh, tokl, nullptr, qfh, qfl}, 192, 1024, 64, 64, 1024, 1024,
       0, 65536, 196608, 32, ZM, 1.f, nullptr, bqkv_f, NEG, POS);
    tg(1, false, {qfh, qfl, qfh + 65536, qfl + 65536, S, nullptr, nullptr}, 1024, 1024, 64, 1024, 1024, 1024,
       196608, 196608, 1048576, 32, ZM, 0.125f, nullptr, nullptr, NEG, POS);
    k_softmax<<<32768, 256>>>(S, Ph, Pl);
    tg(2, true, {qfh + 131072, qfl + 131072, Ph, Pl, outf, nullptr, nullptr}, 64, 1024, 1024, 1024, 1024, 1024,
       196608, 1048576, 65536, 32, ZM, 1.f, nullptr, nullptr, NEG, POS);

    // ---- residual add, depthwise, pointwise
    k_scatter<<<8192, 256>>>();
    k_dw<<<8192, 256>>>(dw_w);
    tg(0, false, {pwh, pwl, t1h, t1l, out, nullptr, nullptr}, 256, 4096, 256, 256, 4096, 4096,
       0, 1048576, 1048576, Bn, ZM, 1.f, b2s, b2h, 0.f, 6.f);
}